// round 1
// baseline (speedup 1.0000x reference)
#include <cuda_runtime.h>
#include <math.h>

#define Nn 10000
#define Ff 256
#define Oo 128
#define Kk 5
#define Ee 160000
#define NC 1408   /* 128 (Y@W) + 5*128 (M@Wk) + 5*128 (M2@Vk) */

// ---------------- scratch (static device arrays; no allocation allowed) ----------------
__device__ float g_xm[Nn * Ff];
__device__ float g_mk[Nn * Ff];
__device__ float g_Y [Nn * Ff];
__device__ float g_M [Nn * Ff];
__device__ float g_M2[Nn * Ff];
__device__ float g_gamma[Nn * Kk];
__device__ float g_degw[Nn];
__device__ float g_Wall[Ff * NC];
__device__ float g_ivar[Kk * Ff];
__device__ float g_D[Nn * NC];
__device__ int   g_cnt[Nn];
__device__ int   g_fill[Nn];
__device__ int   g_rowptr[Nn + 1];
__device__ int   g_scol[Ee];
__device__ float g_sval[Ee];
__device__ int   g_maskmode;

// ---------------- mask dtype detection ----------------
// bool8 mask: words are packed 0/1 bytes -> values like 0x00010001.
// int32 mask: every word is exactly 0 or 1.
// float32 mask: every word is 0 or 0x3F800000.
__global__ void detect_mask_kernel(const unsigned int* m) {
    if (threadIdx.x != 0 || blockIdx.x != 0) return;
    int is_i32 = 1, is_f32 = 1;
    for (int i = 0; i < 1024; i++) {
        unsigned v = m[i];
        if (!(v == 0u || v == 1u)) is_i32 = 0;
        if (!(v == 0u || v == 0x3F800000u)) is_f32 = 0;
    }
    g_maskmode = is_i32 ? 1 : (is_f32 ? 2 : 0);
}

__global__ void zero_counts_kernel() {
    int i = blockIdx.x * blockDim.x + threadIdx.x;
    if (i < Nn) { g_cnt[i] = 0; g_fill[i] = 0; }
}

// Build Wall[f, :]: cols [0,128)=W ; [128+128k)=means[k,f]*W ; [768+128k)=exp(logvar[k,f])*W^2
// Also inv-variance table.
__global__ void prep_weights_kernel(const float* __restrict__ W,
                                    const float* __restrict__ means,
                                    const float* __restrict__ logvars) {
    int idx = blockIdx.x * blockDim.x + threadIdx.x;
    if (idx < Ff * Oo) {
        int f = idx >> 7, o = idx & 127;
        float w = W[f * Oo + o];
        float* row = &g_Wall[f * NC];
        row[o] = w;
#pragma unroll
        for (int k = 0; k < Kk; k++) {
            float m  = means[k * Ff + f];
            float lv = logvars[k * Ff + f];
            row[128 + k * Oo + o] = m * w;
            row[768 + k * Oo + o] = expf(lv) * w * w;
        }
    }
    if (idx < Kk * Ff) g_ivar[idx] = expf(-logvars[idx]);
}

__global__ void hist_kernel(const int* __restrict__ erow) {
    int e = blockIdx.x * blockDim.x + threadIdx.x;
    if (e < Ee) atomicAdd(&g_cnt[erow[e]], 1);
}

// single-block exclusive scan of g_cnt -> g_rowptr
__global__ void scan_kernel() {
    __shared__ int s[1024];
    int t = threadIdx.x;
    const int CH = 10;               // 1024*10 >= 10000
    int loc[CH];
    int sum = 0;
#pragma unroll
    for (int i = 0; i < CH; i++) {
        int idx = t * CH + i;
        int c = (idx < Nn) ? g_cnt[idx] : 0;
        loc[i] = sum; sum += c;
    }
    s[t] = sum;
    __syncthreads();
    for (int off = 1; off < 1024; off <<= 1) {
        int v = (t >= off) ? s[t - off] : 0;
        __syncthreads();
        s[t] += v;
        __syncthreads();
    }
    int pre = (t == 0) ? 0 : s[t - 1];
#pragma unroll
    for (int i = 0; i < CH; i++) {
        int idx = t * CH + i;
        if (idx < Nn) g_rowptr[idx] = pre + loc[i];
    }
    if (t == 1023) g_rowptr[Nn] = s[1023];
}

__global__ void scatter_kernel(const int* __restrict__ erow,
                               const int* __restrict__ ecol,
                               const float* __restrict__ eval) {
    int e = blockIdx.x * blockDim.x + threadIdx.x;
    if (e < Ee) {
        int r = erow[e];
        int pos = g_rowptr[r] + atomicAdd(&g_fill[r], 1);
        g_scol[pos] = ecol[e];
        g_sval[pos] = eval[e];
    }
}

// Per node: expand xm/mk, and gamma[k,n] = softmax_k(logp[k] - 0.5*sum_{f unmasked}(x-mu)^2/var)
__global__ void mask_gamma_kernel(const float* __restrict__ x,
                                  const void* __restrict__ maskp,
                                  const float* __restrict__ means,
                                  const float* __restrict__ logp) {
    int n = blockIdx.x, t = threadIdx.x;   // 256 threads, t == feature
    int idx = n * Ff + t;
    float xv = x[idx];
    int mode = g_maskmode;
    int mm;
    if (mode == 0)      mm = (((const unsigned char*)maskp)[idx] != 0);
    else if (mode == 1) mm = (((const int*)maskp)[idx] != 0);
    else                mm = (((const float*)maskp)[idx] != 0.0f);

    g_xm[idx] = mm ? 0.0f : xv;
    g_mk[idx] = mm ? 1.0f : 0.0f;

    float q[Kk];
#pragma unroll
    for (int k = 0; k < Kk; k++) {
        float d = xv - means[k * Ff + t];
        q[k] = mm ? 0.0f : d * d * g_ivar[k * Ff + t];
    }
#pragma unroll
    for (int off = 16; off; off >>= 1)
#pragma unroll
        for (int k = 0; k < Kk; k++)
            q[k] += __shfl_down_sync(0xffffffffu, q[k], off);

    __shared__ float sq[8][Kk];
    int w = t >> 5, l = t & 31;
    if (l == 0)
#pragma unroll
        for (int k = 0; k < Kk; k++) sq[w][k] = q[k];
    __syncthreads();
    if (t == 0) {
        float logit[Kk];
#pragma unroll
        for (int k = 0; k < Kk; k++) {
            float s = 0.0f;
            for (int w2 = 0; w2 < 8; w2++) s += sq[w2][k];
            logit[k] = logp[k] - 0.5f * s;
        }
        float mx = logit[0];
#pragma unroll
        for (int k = 1; k < Kk; k++) mx = fmaxf(mx, logit[k]);
        float se = 0.0f, e[Kk];
#pragma unroll
        for (int k = 0; k < Kk; k++) { e[k] = expf(logit[k] - mx); se += e[k]; }
#pragma unroll
        for (int k = 0; k < Kk; k++) g_gamma[n * Kk + k] = e[k] / se;
    }
}

// CSR SPMM: Y = S@xm, M = S@mk, M2 = S2@mk, degw = rowsum(S). One block per row.
__global__ void spmm_kernel() {
    int n = blockIdx.x, t = threadIdx.x;   // 256 threads, t == feature
    int s = g_rowptr[n], e = g_rowptr[n + 1];
    __shared__ int   sc[128];
    __shared__ float sv[128];
    float aY = 0.0f, aM = 0.0f, aM2 = 0.0f, dw = 0.0f;
    for (int base = s; base < e; base += 128) {
        int cnt = min(128, e - base);
        if (t < cnt) { sc[t] = g_scol[base + t]; sv[t] = g_sval[base + t]; }
        __syncthreads();
        for (int j = 0; j < cnt; j++) {
            int c = sc[j]; float v = sv[j];
            float xv = g_xm[c * Ff + t];
            float mv = g_mk[c * Ff + t];
            aY  += v * xv;
            aM  += v * mv;
            aM2 += v * v * mv;
            dw  += v;
        }
        __syncthreads();
    }
    int idx = n * Ff + t;
    g_Y [idx] = aY;
    g_M [idx] = aM;
    g_M2[idx] = aM2;
    if (t == 0) g_degw[n] = dw;
}

// GEMM: D[n, cb*128 + ...] = Asrc @ Wall_block.   Asrc: cb==0 -> Y ; 1..5 -> M ; 6..10 -> M2
__global__ __launch_bounds__(256) void gemm_kernel() {
    const int cb = blockIdx.x;   // 0..10
    const int rb = blockIdx.y;   // 0..78
    const float* __restrict__ A = (cb == 0) ? g_Y : ((cb < 6) ? g_M : g_M2);
    const float* __restrict__ B = g_Wall + cb * 128;

    __shared__ float As[16][132];   // padded: avoid store-bank conflicts
    __shared__ float Bs[16][128];

    int tid  = threadIdx.x;
    int arow = tid >> 2, ak = (tid & 3) << 2;   // A tile loader
    int brow = tid >> 5, bc = (tid & 31) << 2;  // B tile loader
    int tr   = tid >> 4, tc = tid & 15;         // 8x8 microtile

    float acc[8][8];
#pragma unroll
    for (int i = 0; i < 8; i++)
#pragma unroll
        for (int j = 0; j < 8; j++) acc[i][j] = 0.0f;

    const int rowbase = rb * 128;
    for (int kt = 0; kt < Ff; kt += 16) {
#pragma unroll
        for (int h = 0; h < 2; h++) {
            int r = arow + h * 64;
            int gr = rowbase + r;
            float4 v = (gr < Nn) ? *(const float4*)&A[gr * Ff + kt + ak]
                                 : make_float4(0.f, 0.f, 0.f, 0.f);
            As[ak + 0][r] = v.x; As[ak + 1][r] = v.y;
            As[ak + 2][r] = v.z; As[ak + 3][r] = v.w;
        }
#pragma unroll
        for (int h = 0; h < 2; h++) {
            int r = brow + h * 8;
            *(float4*)&Bs[r][bc] = *(const float4*)&B[(kt + r) * NC + bc];
        }
        __syncthreads();
#pragma unroll
        for (int kk = 0; kk < 16; kk++) {
            float a[8], b[8];
            *(float4*)&a[0] = *(const float4*)&As[kk][tr * 8];
            *(float4*)&a[4] = *(const float4*)&As[kk][tr * 8 + 4];
            *(float4*)&b[0] = *(const float4*)&Bs[kk][tc * 8];
            *(float4*)&b[4] = *(const float4*)&Bs[kk][tc * 8 + 4];
#pragma unroll
            for (int i = 0; i < 8; i++)
#pragma unroll
                for (int j = 0; j < 8; j++) acc[i][j] += a[i] * b[j];
        }
        __syncthreads();
    }
#pragma unroll
    for (int i = 0; i < 8; i++) {
        int gr = rowbase + tr * 8 + i;
        if (gr < Nn) {
            float* p = &g_D[gr * NC + cb * 128 + tc * 8];
            *(float4*)p       = make_float4(acc[i][0], acc[i][1], acc[i][2], acc[i][3]);
            *(float4*)(p + 4) = make_float4(acc[i][4], acc[i][5], acc[i][6], acc[i][7]);
        }
    }
}

// ex_relu + gamma-weighted sum over components
__global__ void final_kernel(const float* __restrict__ bias, float* __restrict__ out) {
    int n = blockIdx.x, o = threadIdx.x;   // 128 threads
    const float* Dn = &g_D[n * NC];
    float d0 = Dn[o];
    float dw = g_degw[n];
    float bo = bias[o];
    float acc = 0.0f;
#pragma unroll
    for (int k = 0; k < Kk; k++) {
        float cx = d0 + Dn[128 + k * 128 + o] + dw * bo;
        float cc = Dn[768 + k * 128 + o];
        float ex;
        if (cc == 0.0f) {
            ex = fmaxf(cx, 0.0f);
        } else {
            float sq = sqrtf(cc);
            float w  = cx / sq;
            ex = sq * (0.3989422804014327f * expf(-0.5f * w * w)
                       + 0.5f * w * (1.0f + erff(w * 0.70710678118654752f)));
        }
        acc += g_gamma[n * Kk + k] * ex;
    }
    out[n * Oo + o] = acc;
}

extern "C" void kernel_launch(void* const* d_in, const int* in_sizes, int n_in,
                              void* d_out, int out_size) {
    const float* x_vals  = (const float*)d_in[0];
    const void*  x_mask  = (const void*) d_in[1];
    const int*   erow    = (const int*)  d_in[2];
    const int*   ecol    = (const int*)  d_in[3];
    const float* eval    = (const float*)d_in[4];
    const float* logp    = (const float*)d_in[5];
    const float* means   = (const float*)d_in[6];
    const float* logvars = (const float*)d_in[7];
    const float* weight  = (const float*)d_in[8];
    const float* bias    = (const float*)d_in[9];
    float* out = (float*)d_out;
    (void)in_sizes; (void)n_in; (void)out_size;

    detect_mask_kernel<<<1, 32>>>((const unsigned int*)x_mask);
    zero_counts_kernel<<<(Nn + 255) / 256, 256>>>();
    prep_weights_kernel<<<(Ff * Oo + 255) / 256, 256>>>(weight, means, logvars);
    hist_kernel<<<(Ee + 255) / 256, 256>>>(erow);
    scan_kernel<<<1, 1024>>>();
    scatter_kernel<<<(Ee + 255) / 256, 256>>>(erow, ecol, eval);
    mask_gamma_kernel<<<Nn, 256>>>(x_vals, x_mask, means, logp);
    spmm_kernel<<<Nn, 256>>>();
    dim3 gg(11, 79);
    gemm_kernel<<<gg, 256>>>();
    final_kernel<<<Nn, 128>>>(bias, out);
}

// round 3
// speedup vs baseline: 1.5742x; 1.5742x over previous
#include <cuda_runtime.h>
#include <math.h>

#define Nn 10000
#define Ff 256
#define Oo 128
#define Kk 5
#define Ee 160000
#define NC 1408   /* 128 (Y@W) + 5*128 (M@Wk) + 5*128 (M2@Vk) */

// ---------------- scratch (static device arrays; no allocation allowed) ----------------
__device__ float g_xm[Nn * Ff];
__device__ float g_mk[Nn * Ff];
__device__ float g_Y [Nn * Ff];
__device__ float g_M [Nn * Ff];
__device__ float g_M2[Nn * Ff];
__device__ float g_gamma[Nn * Kk];
__device__ float g_degw[Nn];
__device__ float g_Wall[Ff * NC];
__device__ float g_ivar[Kk * Ff];
__device__ float g_D[Nn * NC];
__device__ int   g_cnt[Nn];
__device__ int   g_fill[Nn];
__device__ int   g_rowptr[Nn + 1];
__device__ int   g_scol[Ee];
__device__ float g_sval[Ee];
__device__ int   g_maskmode;

// tf32 round-to-nearest; tf32 cvt destination must be a b32 register.
__device__ __forceinline__ float tf32r(float x) {
    unsigned u;
    asm("cvt.rna.tf32.f32 %0, %1;" : "=r"(u) : "f"(x));
    return __uint_as_float(u);
}

// ---------------- mask dtype detection (parallel) ----------------
__global__ void detect_mask_kernel(const unsigned int* m) {
    int t = threadIdx.x;
    int i32ok = 1, f32ok = 1;
    for (int i = t; i < 1024; i += 256) {
        unsigned v = m[i];
        if (v > 1u) i32ok = 0;
        if (!(v == 0u || v == 0x3F800000u)) f32ok = 0;
    }
    int allI = __syncthreads_and(i32ok);
    int allF = __syncthreads_and(f32ok);
    if (t == 0) g_maskmode = allI ? 1 : (allF ? 2 : 0);
}

__global__ void zero_counts_kernel() {
    int i = blockIdx.x * blockDim.x + threadIdx.x;
    if (i < Nn) { g_cnt[i] = 0; g_fill[i] = 0; }
}

// Build Wall[f, :] (tf32-rounded): [0,128)=W ; [128+128k)=means[k,f]*W ; [768+128k)=exp(lv)*W^2
__global__ void prep_weights_kernel(const float* __restrict__ W,
                                    const float* __restrict__ means,
                                    const float* __restrict__ logvars) {
    int idx = blockIdx.x * blockDim.x + threadIdx.x;
    if (idx < Ff * Oo) {
        int f = idx >> 7, o = idx & 127;
        float w = W[f * Oo + o];
        float* row = &g_Wall[f * NC];
        row[o] = tf32r(w);
#pragma unroll
        for (int k = 0; k < Kk; k++) {
            float m  = means[k * Ff + f];
            float lv = logvars[k * Ff + f];
            row[128 + k * Oo + o] = tf32r(m * w);
            row[768 + k * Oo + o] = tf32r(expf(lv) * w * w);
        }
    }
    if (idx < Kk * Ff) g_ivar[idx] = expf(-logvars[idx]);
}

__global__ void hist_kernel(const int* __restrict__ erow) {
    int e = blockIdx.x * blockDim.x + threadIdx.x;
    if (e < Ee) atomicAdd(&g_cnt[erow[e]], 1);
}

// single-block exclusive scan of g_cnt -> g_rowptr
__global__ void scan_kernel() {
    __shared__ int s[1024];
    int t = threadIdx.x;
    const int CH = 10;
    int loc[CH];
    int sum = 0;
#pragma unroll
    for (int i = 0; i < CH; i++) {
        int idx = t * CH + i;
        int c = (idx < Nn) ? g_cnt[idx] : 0;
        loc[i] = sum; sum += c;
    }
    s[t] = sum;
    __syncthreads();
    for (int off = 1; off < 1024; off <<= 1) {
        int v = (t >= off) ? s[t - off] : 0;
        __syncthreads();
        s[t] += v;
        __syncthreads();
    }
    int pre = (t == 0) ? 0 : s[t - 1];
#pragma unroll
    for (int i = 0; i < CH; i++) {
        int idx = t * CH + i;
        if (idx < Nn) g_rowptr[idx] = pre + loc[i];
    }
    if (t == 1023) g_rowptr[Nn] = s[1023];
}

__global__ void scatter_kernel(const int* __restrict__ erow,
                               const int* __restrict__ ecol,
                               const float* __restrict__ eval) {
    int e = blockIdx.x * blockDim.x + threadIdx.x;
    if (e < Ee) {
        int r = erow[e];
        int pos = g_rowptr[r] + atomicAdd(&g_fill[r], 1);
        g_scol[pos] = ecol[e];
        g_sval[pos] = eval[e];
    }
}

// Per node: expand xm/mk, and gamma[k,n] = softmax_k(logp[k] - 0.5*sum_{f unmasked}(x-mu)^2/var)
__global__ void mask_gamma_kernel(const float* __restrict__ x,
                                  const void* __restrict__ maskp,
                                  const float* __restrict__ means,
                                  const float* __restrict__ logp) {
    int n = blockIdx.x, t = threadIdx.x;   // 256 threads, t == feature
    int idx = n * Ff + t;
    float xv = x[idx];
    int mode = g_maskmode;
    int mm;
    if (mode == 0)      mm = (((const unsigned char*)maskp)[idx] != 0);
    else if (mode == 1) mm = (((const int*)maskp)[idx] != 0);
    else                mm = (((const float*)maskp)[idx] != 0.0f);

    g_xm[idx] = mm ? 0.0f : xv;
    g_mk[idx] = mm ? 1.0f : 0.0f;

    float q[Kk];
#pragma unroll
    for (int k = 0; k < Kk; k++) {
        float d = xv - means[k * Ff + t];
        q[k] = mm ? 0.0f : d * d * g_ivar[k * Ff + t];
    }
#pragma unroll
    for (int off = 16; off; off >>= 1)
#pragma unroll
        for (int k = 0; k < Kk; k++)
            q[k] += __shfl_down_sync(0xffffffffu, q[k], off);

    __shared__ float sq[8][Kk];
    int w = t >> 5, l = t & 31;
    if (l == 0)
#pragma unroll
        for (int k = 0; k < Kk; k++) sq[w][k] = q[k];
    __syncthreads();
    if (t == 0) {
        float logit[Kk];
#pragma unroll
        for (int k = 0; k < Kk; k++) {
            float s = 0.0f;
            for (int w2 = 0; w2 < 8; w2++) s += sq[w2][k];
            logit[k] = logp[k] - 0.5f * s;
        }
        float mx = logit[0];
#pragma unroll
        for (int k = 1; k < Kk; k++) mx = fmaxf(mx, logit[k]);
        float se = 0.0f, e[Kk];
#pragma unroll
        for (int k = 0; k < Kk; k++) { e[k] = expf(logit[k] - mx); se += e[k]; }
#pragma unroll
        for (int k = 0; k < Kk; k++) g_gamma[n * Kk + k] = e[k] / se;
    }
}

// CSR SPMM: Y = S@xm, M = S@mk, M2 = S2@mk, degw = rowsum(S). One block per row.
// Outputs tf32-rounded (they feed only the tensor-core GEMM).
__global__ void spmm_kernel() {
    int n = blockIdx.x, t = threadIdx.x;   // 256 threads, t == feature
    int s = g_rowptr[n], e = g_rowptr[n + 1];
    __shared__ int   sc[128];
    __shared__ float sv[128];
    float aY = 0.0f, aM = 0.0f, aM2 = 0.0f, dw = 0.0f;
    for (int base = s; base < e; base += 128) {
        int cnt = min(128, e - base);
        if (t < cnt) { sc[t] = g_scol[base + t]; sv[t] = g_sval[base + t]; }
        __syncthreads();
        for (int j = 0; j < cnt; j++) {
            int c = sc[j]; float v = sv[j];
            float xv = g_xm[c * Ff + t];
            float mv = g_mk[c * Ff + t];
            aY  += v * xv;
            aM  += v * mv;
            aM2 += v * v * mv;
            dw  += v;
        }
        __syncthreads();
    }
    int idx = n * Ff + t;
    g_Y [idx] = tf32r(aY);
    g_M [idx] = tf32r(aM);
    g_M2[idx] = tf32r(aM2);
    if (t == 0) g_degw[n] = dw;
}

// ---------------- tf32 mma.sync GEMM ----------------
// D[n, cb*128 + j] = Asrc @ Wall_block.  Asrc: cb==0 -> Y ; 1..5 -> M ; 6..10 -> M2
// BM=128, BN=128, BK=32, 8 warps (4 along M x 2 along N), warp tile 32x64,
// mma m16n8k8 tf32, fp32 accumulate. Inputs already tf32-rounded.
__global__ __launch_bounds__(256, 2) void gemm_kernel() {
    const int cb = blockIdx.x;   // 0..10
    const int rb = blockIdx.y;   // 0..78
    const float* __restrict__ A = (cb == 0) ? g_Y : ((cb < 6) ? g_M : g_M2);
    const float* __restrict__ B = g_Wall + cb * 128;

    __shared__ float As[32][132];   // [k][m], padded
    __shared__ float Bs[32][132];   // [k][n], padded

    const int tid  = threadIdx.x;
    const int lane = tid & 31, w = tid >> 5;
    const int wm = (w & 3) * 32;        // warp M offset
    const int wn = (w >> 2) * 64;       // warp N offset
    const int lr = lane >> 2, lc = lane & 3;
    const int rowbase = rb * 128;

    // loader indices
    const int am   = tid >> 1;          // A: row within tile (0..127)
    const int ach0 = (tid & 1) * 4;     // A: first k-chunk (0 or 4) of 4
    const int br   = tid >> 3;          // B: k row (0..31)
    const int bc0  = (tid & 7) * 4;     // B: first col chunk

    float acc[2][8][4];
#pragma unroll
    for (int mt = 0; mt < 2; mt++)
#pragma unroll
        for (int nt = 0; nt < 8; nt++)
#pragma unroll
            for (int i = 0; i < 4; i++) acc[mt][nt][i] = 0.0f;

    const int gr = rowbase + am;
    const bool arow_ok = (gr < Nn);
    const float* Arow = A + (size_t)gr * Ff;
    const float* Brow = B + (size_t)br * NC;

    for (int kt = 0; kt < Ff; kt += 32) {
        // load A tile (transposed into [k][m])
#pragma unroll
        for (int j = 0; j < 4; j++) {
            int ch = ach0 + j;               // 0..7
            float4 v = arow_ok ? *(const float4*)&Arow[kt + ch * 4]
                               : make_float4(0.f, 0.f, 0.f, 0.f);
            As[ch * 4 + 0][am] = v.x;
            As[ch * 4 + 1][am] = v.y;
            As[ch * 4 + 2][am] = v.z;
            As[ch * 4 + 3][am] = v.w;
        }
        // load B tile (direct row copy)
#pragma unroll
        for (int h = 0; h < 4; h++) {
            int c = bc0 + h * 32;
            *(float4*)&Bs[br][c] = *(const float4*)&Brow[(size_t)kt * NC + c];
        }
        __syncthreads();

#pragma unroll
        for (int ks = 0; ks < 4; ks++) {
            const int kb = ks * 8;
            unsigned a[2][4], b[8][2];
#pragma unroll
            for (int mt = 0; mt < 2; mt++) {
                int mr = wm + mt * 16 + lr;
                a[mt][0] = __float_as_uint(As[kb + lc    ][mr    ]);
                a[mt][1] = __float_as_uint(As[kb + lc    ][mr + 8]);
                a[mt][2] = __float_as_uint(As[kb + lc + 4][mr    ]);
                a[mt][3] = __float_as_uint(As[kb + lc + 4][mr + 8]);
            }
#pragma unroll
            for (int nt = 0; nt < 8; nt++) {
                int nc2 = wn + nt * 8 + lr;
                b[nt][0] = __float_as_uint(Bs[kb + lc    ][nc2]);
                b[nt][1] = __float_as_uint(Bs[kb + lc + 4][nc2]);
            }
#pragma unroll
            for (int mt = 0; mt < 2; mt++)
#pragma unroll
                for (int nt = 0; nt < 8; nt++) {
                    asm volatile(
                        "mma.sync.aligned.m16n8k8.row.col.f32.tf32.tf32.f32 "
                        "{%0,%1,%2,%3}, {%4,%5,%6,%7}, {%8,%9}, {%0,%1,%2,%3};"
                        : "+f"(acc[mt][nt][0]), "+f"(acc[mt][nt][1]),
                          "+f"(acc[mt][nt][2]), "+f"(acc[mt][nt][3])
                        : "r"(a[mt][0]), "r"(a[mt][1]), "r"(a[mt][2]), "r"(a[mt][3]),
                          "r"(b[nt][0]), "r"(b[nt][1]));
                }
        }
        __syncthreads();
    }

    // store
#pragma unroll
    for (int mt = 0; mt < 2; mt++) {
        int r0 = rowbase + wm + mt * 16 + lr;
#pragma unroll
        for (int nt = 0; nt < 8; nt++) {
            int col = cb * 128 + wn + nt * 8 + lc * 2;
            if (r0 < Nn)
                *(float2*)&g_D[(size_t)r0 * NC + col] =
                    make_float2(acc[mt][nt][0], acc[mt][nt][1]);
            if (r0 + 8 < Nn)
                *(float2*)&g_D[(size_t)(r0 + 8) * NC + col] =
                    make_float2(acc[mt][nt][2], acc[mt][nt][3]);
        }
    }
}

// ex_relu + gamma-weighted sum over components
__global__ void final_kernel(const float* __restrict__ bias, float* __restrict__ out) {
    int n = blockIdx.x, o = threadIdx.x;   // 128 threads
    const float* Dn = &g_D[(size_t)n * NC];
    float d0 = Dn[o];
    float dw = g_degw[n];
    float bo = bias[o];
    float acc = 0.0f;
#pragma unroll
    for (int k = 0; k < Kk; k++) {
        float cx = d0 + Dn[128 + k * 128 + o] + dw * bo;
        float cc = Dn[768 + k * 128 + o];
        float ex;
        if (cc == 0.0f) {
            ex = fmaxf(cx, 0.0f);
        } else {
            float sq = sqrtf(cc);
            float w  = cx / sq;
            ex = sq * (0.3989422804014327f * expf(-0.5f * w * w)
                       + 0.5f * w * (1.0f + erff(w * 0.70710678118654752f)));
        }
        acc += g_gamma[n * Kk + k] * ex;
    }
    out[n * Oo + o] = acc;
}

extern "C" void kernel_launch(void* const* d_in, const int* in_sizes, int n_in,
                              void* d_out, int out_size) {
    const float* x_vals  = (const float*)d_in[0];
    const void*  x_mask  = (const void*) d_in[1];
    const int*   erow    = (const int*)  d_in[2];
    const int*   ecol    = (const int*)  d_in[3];
    const float* eval    = (const float*)d_in[4];
    const float* logp    = (const float*)d_in[5];
    const float* means   = (const float*)d_in[6];
    const float* logvars = (const float*)d_in[7];
    const float* weight  = (const float*)d_in[8];
    const float* bias    = (const float*)d_in[9];
    float* out = (float*)d_out;
    (void)in_sizes; (void)n_in; (void)out_size;

    detect_mask_kernel<<<1, 256>>>((const unsigned int*)x_mask);
    zero_counts_kernel<<<(Nn + 255) / 256, 256>>>();
    prep_weights_kernel<<<(Ff * Oo + 255) / 256, 256>>>(weight, means, logvars);
    hist_kernel<<<(Ee + 255) / 256, 256>>>(erow);
    scan_kernel<<<1, 1024>>>();
    scatter_kernel<<<(Ee + 255) / 256, 256>>>(erow, ecol, eval);
    mask_gamma_kernel<<<Nn, 256>>>(x_vals, x_mask, means, logp);
    spmm_kernel<<<Nn, 256>>>();
    dim3 gg(11, 79);
    gemm_kernel<<<gg, 256>>>();
    final_kernel<<<Nn, 128>>>(bias, out);
}

// round 4
// speedup vs baseline: 1.7619x; 1.1192x over previous
#include <cuda_runtime.h>
#include <math.h>

#define Nn 10000
#define Ff 256
#define Oo 128
#define Kk 5
#define Ee 160000
#define NC 1408   /* 128 (Y@W) + 5*128 (M@Wk) + 5*128 (M2@Vk) */

// ---------------- scratch ----------------
__device__ float g_xm[Nn * Ff];
__device__ unsigned char g_mku[Nn * Ff];
__device__ float g_Y [Nn * Ff];
__device__ float g_M [Nn * Ff];
__device__ float g_M2[Nn * Ff];
__device__ float g_gamma[Nn * Kk];
__device__ float g_degw[Nn];
__device__ float g_Wall[Ff * NC];
__device__ float g_ivar[Kk * Ff];
__device__ float g_D[Nn * NC];
__device__ int   g_cnt[Nn];
__device__ int   g_fill[Nn];
__device__ int   g_rowptr[Nn + 1];
__device__ int   g_scol[Ee];
__device__ float g_sval[Ee];
__device__ int   g_maskmode;

__device__ __forceinline__ float tf32r(float x) {
    unsigned u;
    asm("cvt.rna.tf32.f32 %0, %1;" : "=r"(u) : "f"(x));
    return __uint_as_float(u);
}

__device__ __forceinline__ void cp_async16(unsigned smem_addr, const void* gptr, bool pred) {
    int bytes = pred ? 16 : 0;
    asm volatile("cp.async.cg.shared.global [%0], [%1], 16, %2;\n"
                 :: "r"(smem_addr), "l"(gptr), "r"(bytes));
}
__device__ __forceinline__ void cp_async_commit() {
    asm volatile("cp.async.commit_group;\n");
}
template<int N> __device__ __forceinline__ void cp_async_wait() {
    asm volatile("cp.async.wait_group %0;\n" :: "n"(N));
}

// ---------------- init: zero counters (all blocks) + mask dtype detection (block 0) ----------------
__global__ void init_kernel(const unsigned int* m) {
    int t = blockIdx.x * blockDim.x + threadIdx.x;
    for (int i = t; i < Nn; i += gridDim.x * blockDim.x) { g_cnt[i] = 0; g_fill[i] = 0; }
    if (blockIdx.x == 0) {
        int tt = threadIdx.x;
        int i32ok = 1, f32ok = 1;
        for (int i = tt; i < 1024; i += 256) {
            unsigned v = m[i];
            if (v > 1u) i32ok = 0;
            if (!(v == 0u || v == 0x3F800000u)) f32ok = 0;
        }
        int allI = __syncthreads_and(i32ok);
        int allF = __syncthreads_and(f32ok);
        if (tt == 0) g_maskmode = allI ? 1 : (allF ? 2 : 0);
    }
}

// Build Wall[f, :] (tf32-rounded): [0,128)=W ; [128+128k)=means[k,f]*W ; [768+128k)=exp(lv)*W^2
__global__ void prep_weights_kernel(const float* __restrict__ W,
                                    const float* __restrict__ means,
                                    const float* __restrict__ logvars) {
    int idx = blockIdx.x * blockDim.x + threadIdx.x;
    if (idx < Ff * Oo) {
        int f = idx >> 7, o = idx & 127;
        float w = W[f * Oo + o];
        float* row = &g_Wall[f * NC];
        row[o] = tf32r(w);
#pragma unroll
        for (int k = 0; k < Kk; k++) {
            float m  = means[k * Ff + f];
            float lv = logvars[k * Ff + f];
            row[128 + k * Oo + o] = tf32r(m * w);
            row[768 + k * Oo + o] = tf32r(expf(lv) * w * w);
        }
    }
    if (idx < Kk * Ff) g_ivar[idx] = expf(-logvars[idx]);
}

__global__ void hist_kernel(const int* __restrict__ erow) {
    int e = blockIdx.x * blockDim.x + threadIdx.x;
    if (e < Ee) atomicAdd(&g_cnt[erow[e]], 1);
}

// single-block exclusive scan of g_cnt -> g_rowptr
__global__ void scan_kernel() {
    __shared__ int s[1024];
    int t = threadIdx.x;
    const int CH = 10;
    int loc[CH];
    int sum = 0;
#pragma unroll
    for (int i = 0; i < CH; i++) {
        int idx = t * CH + i;
        int c = (idx < Nn) ? g_cnt[idx] : 0;
        loc[i] = sum; sum += c;
    }
    s[t] = sum;
    __syncthreads();
    for (int off = 1; off < 1024; off <<= 1) {
        int v = (t >= off) ? s[t - off] : 0;
        __syncthreads();
        s[t] += v;
        __syncthreads();
    }
    int pre = (t == 0) ? 0 : s[t - 1];
#pragma unroll
    for (int i = 0; i < CH; i++) {
        int idx = t * CH + i;
        if (idx < Nn) g_rowptr[idx] = pre + loc[i];
    }
    if (t == 1023) g_rowptr[Nn] = s[1023];
}

__global__ void scatter_kernel(const int* __restrict__ erow,
                               const int* __restrict__ ecol,
                               const float* __restrict__ eval) {
    int e = blockIdx.x * blockDim.x + threadIdx.x;
    if (e < Ee) {
        int r = erow[e];
        int pos = g_rowptr[r] + atomicAdd(&g_fill[r], 1);
        g_scol[pos] = ecol[e];
        g_sval[pos] = eval[e];
    }
}

// Per node: expand xm / mk(u8), and gamma[k,n]
__global__ void mask_gamma_kernel(const float* __restrict__ x,
                                  const void* __restrict__ maskp,
                                  const float* __restrict__ means,
                                  const float* __restrict__ logp) {
    int n = blockIdx.x, t = threadIdx.x;   // 256 threads, t == feature
    int idx = n * Ff + t;
    float xv = x[idx];
    int mode = g_maskmode;
    int mm;
    if (mode == 0)      mm = (((const unsigned char*)maskp)[idx] != 0);
    else if (mode == 1) mm = (((const int*)maskp)[idx] != 0);
    else                mm = (((const float*)maskp)[idx] != 0.0f);

    g_xm[idx]  = mm ? 0.0f : xv;
    g_mku[idx] = (unsigned char)mm;

    float q[Kk];
#pragma unroll
    for (int k = 0; k < Kk; k++) {
        float d = xv - means[k * Ff + t];
        q[k] = mm ? 0.0f : d * d * g_ivar[k * Ff + t];
    }
#pragma unroll
    for (int off = 16; off; off >>= 1)
#pragma unroll
        for (int k = 0; k < Kk; k++)
            q[k] += __shfl_down_sync(0xffffffffu, q[k], off);

    __shared__ float sq[8][Kk];
    int w = t >> 5, l = t & 31;
    if (l == 0)
#pragma unroll
        for (int k = 0; k < Kk; k++) sq[w][k] = q[k];
    __syncthreads();
    if (t == 0) {
        float logit[Kk];
#pragma unroll
        for (int k = 0; k < Kk; k++) {
            float s = 0.0f;
            for (int w2 = 0; w2 < 8; w2++) s += sq[w2][k];
            logit[k] = logp[k] - 0.5f * s;
        }
        float mx = logit[0];
#pragma unroll
        for (int k = 1; k < Kk; k++) mx = fmaxf(mx, logit[k]);
        float se = 0.0f, e[Kk];
#pragma unroll
        for (int k = 0; k < Kk; k++) { e[k] = expf(logit[k] - mx); se += e[k]; }
#pragma unroll
        for (int k = 0; k < Kk; k++) g_gamma[n * Kk + k] = e[k] / se;
    }
}

// CSR SPMM: Y = S@xm, M = S@mk, M2 = S2@mk, degw = rowsum(S). One block per row.
__global__ void spmm_kernel() {
    int n = blockIdx.x, t = threadIdx.x;   // 256 threads, t == feature
    int s = g_rowptr[n], e = g_rowptr[n + 1];
    __shared__ int   sc[128];
    __shared__ float sv[128];
    float aY = 0.0f, aM = 0.0f, aM2 = 0.0f, dw = 0.0f;
    for (int base = s; base < e; base += 128) {
        int cnt = min(128, e - base);
        if (t < cnt) { sc[t] = g_scol[base + t]; sv[t] = g_sval[base + t]; }
        __syncthreads();
        for (int j = 0; j < cnt; j++) {
            int c = sc[j]; float v = sv[j];
            float xv = g_xm[c * Ff + t];
            float mv = (float)g_mku[c * Ff + t];
            aY  += v * xv;
            aM  += v * mv;
            aM2 += v * v * mv;
            dw  += v;
        }
        __syncthreads();
    }
    int idx = n * Ff + t;
    g_Y [idx] = tf32r(aY);
    g_M [idx] = tf32r(aM);
    g_M2[idx] = tf32r(aM2);
    if (t == 0) g_degw[n] = dw;
}

// ---------------- tf32 mma.sync GEMM, cp.async double-buffered ----------------
// D[n, cb*128 + j] = Asrc @ Wall_block.  Asrc: cb==0 -> Y ; 1..5 -> M ; 6..10 -> M2
// BM=128, BN=128, BK=32, 8 warps (4 M x 2 N), warp tile 32x64, m16n8k8 tf32.
#define AS_STRIDE 36           /* [m][k] pad: (m*36+k)%32 = (m*4+k)%32 -> conflict-free frags */
#define BS_STRIDE 132
#define AS_BUF (128 * AS_STRIDE)
#define BS_BUF (32 * BS_STRIDE)
#define GEMM_SMEM ((2 * AS_BUF + 2 * BS_BUF) * (int)sizeof(float))

__global__ __launch_bounds__(256) void gemm_kernel() {
    extern __shared__ float smem[];
    float* As = smem;                 // [2][128][36]
    float* Bs = smem + 2 * AS_BUF;    // [2][32][132]

    const int cb = blockIdx.x;   // 0..10
    const int rb = blockIdx.y;   // 0..78
    const float* __restrict__ A = (cb == 0) ? g_Y : ((cb < 6) ? g_M : g_M2);
    const float* __restrict__ B = g_Wall + cb * 128;

    const int tid  = threadIdx.x;
    const int lane = tid & 31, w = tid >> 5;
    const int wm = (w & 3) * 32;
    const int wn = (w >> 2) * 64;
    const int lr = lane >> 2, lc = lane & 3;
    const int rowbase = rb * 128;

    // A loader: thread -> row = tid>>1 (0..127), half = tid&1; 4 chunks of 16B
    const int arow = tid >> 1;
    const int ahalf = (tid & 1) * 16;       // float offset within 32-float row
    const int gr = rowbase + arow;
    const bool arow_ok = (gr < Nn);
    const float* Arow = A + (size_t)gr * Ff;
    // B loader: thread -> brow = tid>>3 (0..31), 4 chunks
    const int brow = tid >> 3;
    const int bcol0 = (tid & 7) * 4;        // float offset, chunks at +0,+32,+64,+96
    const float* Brow = B + (size_t)brow * NC;

    unsigned as_base = (unsigned)__cvta_generic_to_shared(As);
    unsigned bs_base = (unsigned)__cvta_generic_to_shared(Bs);

    float acc[2][8][4];
#pragma unroll
    for (int mt = 0; mt < 2; mt++)
#pragma unroll
        for (int nt = 0; nt < 8; nt++)
#pragma unroll
            for (int i = 0; i < 4; i++) acc[mt][nt][i] = 0.0f;

#define LOAD_TILE(KT, BUF) do {                                                     \
        unsigned adst = as_base + (unsigned)(((BUF) * AS_BUF + arow * AS_STRIDE + ahalf) * 4); \
        const float* asrc = Arow + (KT) + ahalf;                                    \
        _Pragma("unroll")                                                           \
        for (int j = 0; j < 4; j++)                                                 \
            cp_async16(adst + j * 16u, asrc + j * 4, arow_ok);                      \
        unsigned bdst = bs_base + (unsigned)(((BUF) * BS_BUF + brow * BS_STRIDE + bcol0) * 4); \
        const float* bsrc = Brow + (size_t)(KT) * NC + bcol0;                       \
        _Pragma("unroll")                                                           \
        for (int j = 0; j < 4; j++)                                                 \
            cp_async16(bdst + j * 128u, bsrc + j * 32, true);                       \
    } while (0)

    LOAD_TILE(0, 0);
    cp_async_commit();

    for (int kt = 0; kt < 8; kt++) {
        if (kt < 7) {
            LOAD_TILE((kt + 1) * 32, (kt + 1) & 1);
            cp_async_commit();
            cp_async_wait<1>();
        } else {
            cp_async_wait<0>();
        }
        __syncthreads();

        const float* Ab = As + (kt & 1) * AS_BUF;
        const float* Bb = Bs + (kt & 1) * BS_BUF;
#pragma unroll
        for (int ks = 0; ks < 4; ks++) {
            const int kb = ks * 8;
            unsigned a[2][4], b[8][2];
#pragma unroll
            for (int mt = 0; mt < 2; mt++) {
                int mr = wm + mt * 16 + lr;
                a[mt][0] = __float_as_uint(Ab[ mr      * AS_STRIDE + kb + lc    ]);
                a[mt][1] = __float_as_uint(Ab[(mr + 8) * AS_STRIDE + kb + lc    ]);
                a[mt][2] = __float_as_uint(Ab[ mr      * AS_STRIDE + kb + lc + 4]);
                a[mt][3] = __float_as_uint(Ab[(mr + 8) * AS_STRIDE + kb + lc + 4]);
            }
#pragma unroll
            for (int nt = 0; nt < 8; nt++) {
                int nc2 = wn + nt * 8 + lr;
                b[nt][0] = __float_as_uint(Bb[(kb + lc    ) * BS_STRIDE + nc2]);
                b[nt][1] = __float_as_uint(Bb[(kb + lc + 4) * BS_STRIDE + nc2]);
            }
#pragma unroll
            for (int mt = 0; mt < 2; mt++)
#pragma unroll
                for (int nt = 0; nt < 8; nt++) {
                    asm volatile(
                        "mma.sync.aligned.m16n8k8.row.col.f32.tf32.tf32.f32 "
                        "{%0,%1,%2,%3}, {%4,%5,%6,%7}, {%8,%9}, {%0,%1,%2,%3};"
                        : "+f"(acc[mt][nt][0]), "+f"(acc[mt][nt][1]),
                          "+f"(acc[mt][nt][2]), "+f"(acc[mt][nt][3])
                        : "r"(a[mt][0]), "r"(a[mt][1]), "r"(a[mt][2]), "r"(a[mt][3]),
                          "r"(b[nt][0]), "r"(b[nt][1]));
                }
        }
        __syncthreads();
    }
#undef LOAD_TILE

#pragma unroll
    for (int mt = 0; mt < 2; mt++) {
        int r0 = rowbase + wm + mt * 16 + lr;
#pragma unroll
        for (int nt = 0; nt < 8; nt++) {
            int col = cb * 128 + wn + nt * 8 + lc * 2;
            if (r0 < Nn)
                *(float2*)&g_D[(size_t)r0 * NC + col] =
                    make_float2(acc[mt][nt][0], acc[mt][nt][1]);
            if (r0 + 8 < Nn)
                *(float2*)&g_D[(size_t)(r0 + 8) * NC + col] =
                    make_float2(acc[mt][nt][2], acc[mt][nt][3]);
        }
    }
}

// ex_relu + gamma-weighted sum over components
__global__ void final_kernel(const float* __restrict__ bias, float* __restrict__ out) {
    int n = blockIdx.x, o = threadIdx.x;   // 128 threads
    const float* Dn = &g_D[(size_t)n * NC];
    float d0 = Dn[o];
    float dw = g_degw[n];
    float bo = bias[o];
    float acc = 0.0f;
#pragma unroll
    for (int k = 0; k < Kk; k++) {
        float cx = d0 + Dn[128 + k * 128 + o] + dw * bo;
        float cc = Dn[768 + k * 128 + o];
        float ex;
        if (cc == 0.0f) {
            ex = fmaxf(cx, 0.0f);
        } else {
            float sq = sqrtf(cc);
            float w  = cx / sq;
            ex = sq * (0.3989422804014327f * expf(-0.5f * w * w)
                       + 0.5f * w * (1.0f + erff(w * 0.70710678118654752f)));
        }
        acc += g_gamma[n * Kk + k] * ex;
    }
    out[n * Oo + o] = acc;
}

extern "C" void kernel_launch(void* const* d_in, const int* in_sizes, int n_in,
                              void* d_out, int out_size) {
    const float* x_vals  = (const float*)d_in[0];
    const void*  x_mask  = (const void*) d_in[1];
    const int*   erow    = (const int*)  d_in[2];
    const int*   ecol    = (const int*)  d_in[3];
    const float* eval    = (const float*)d_in[4];
    const float* logp    = (const float*)d_in[5];
    const float* means   = (const float*)d_in[6];
    const float* logvars = (const float*)d_in[7];
    const float* weight  = (const float*)d_in[8];
    const float* bias    = (const float*)d_in[9];
    float* out = (float*)d_out;
    (void)in_sizes; (void)n_in; (void)out_size;

    static int smem_set = 0;
    if (!smem_set) {
        cudaFuncSetAttribute(gemm_kernel, cudaFuncAttributeMaxDynamicSharedMemorySize, GEMM_SMEM);
        smem_set = 1;
    }

    init_kernel<<<40, 256>>>((const unsigned int*)x_mask);
    prep_weights_kernel<<<(Ff * Oo + 255) / 256, 256>>>(weight, means, logvars);
    hist_kernel<<<(Ee + 255) / 256, 256>>>(erow);
    scan_kernel<<<1, 1024>>>();
    scatter_kernel<<<(Ee + 255) / 256, 256>>>(erow, ecol, eval);
    mask_gamma_kernel<<<Nn, 256>>>(x_vals, x_mask, means, logp);
    spmm_kernel<<<Nn, 256>>>();
    dim3 gg(11, 79);
    gemm_kernel<<<gg, 256, GEMM_SMEM>>>();
    final_kernel<<<Nn, 128>>>(bias, out);
}

// round 5
// speedup vs baseline: 1.7851x; 1.0132x over previous
#include <cuda_runtime.h>
#include <math.h>

#define Nn 10000
#define Ff 256
#define Oo 128
#define Kk 5
#define Ee 160000
#define NC 1408   /* 128 (Y@W) + 5*128 (M@Wk) + 5*128 (M2@Vk) */

// ---------------- scratch ----------------
__device__ float g_xm[Nn * Ff];
__device__ unsigned g_mkb[Nn * 8];      // bit-packed mask, 256 bits per row
__device__ float g_Y [Nn * Ff];
__device__ float g_M [Nn * Ff];
__device__ float g_M2[Nn * Ff];
__device__ float g_gamma[Nn * Kk];
__device__ float g_degw[Nn];
__device__ float g_Wall[Ff * NC];
__device__ float g_ivar[Kk * Ff];
__device__ float g_D[Nn * NC];
__device__ int   g_cnt[Nn];             // zero at entry; re-zeroed by scan_kernel
__device__ int   g_fill[Nn];            // zero at entry; re-zeroed by final_kernel
__device__ int   g_rowptr[Nn + 1];
__device__ int   g_scol[Ee];
__device__ float g_sval[Ee];
__device__ int   g_maskmode;

__device__ __forceinline__ float tf32r(float x) {
    unsigned u;
    asm("cvt.rna.tf32.f32 %0, %1;" : "=r"(u) : "f"(x));
    return __uint_as_float(u);
}

__device__ __forceinline__ void cp_async16(unsigned smem_addr, const void* gptr, bool pred) {
    int bytes = pred ? 16 : 0;
    asm volatile("cp.async.cg.shared.global [%0], [%1], 16, %2;\n"
                 :: "r"(smem_addr), "l"(gptr), "r"(bytes));
}
__device__ __forceinline__ void cp_async_commit() {
    asm volatile("cp.async.commit_group;\n");
}
template<int N> __device__ __forceinline__ void cp_async_wait() {
    asm volatile("cp.async.wait_group %0;\n" :: "n"(N));
}

// ---------------- mask dtype detection ----------------
__global__ void detect_mask_kernel(const unsigned int* m) {
    int t = threadIdx.x;
    int i32ok = 1, f32ok = 1;
    for (int i = t; i < 1024; i += 256) {
        unsigned v = m[i];
        if (v > 1u) i32ok = 0;
        if (!(v == 0u || v == 0x3F800000u)) f32ok = 0;
    }
    int allI = __syncthreads_and(i32ok);
    int allF = __syncthreads_and(f32ok);
    if (t == 0) g_maskmode = allI ? 1 : (allF ? 2 : 0);
}

// Build Wall[f, :] (tf32-rounded): [0,128)=W ; [128+128k)=means[k,f]*W ; [768+128k)=exp(lv)*W^2
__global__ void prep_weights_kernel(const float* __restrict__ W,
                                    const float* __restrict__ means,
                                    const float* __restrict__ logvars) {
    int idx = blockIdx.x * blockDim.x + threadIdx.x;
    if (idx < Ff * Oo) {
        int f = idx >> 7, o = idx & 127;
        float w = W[f * Oo + o];
        float* row = &g_Wall[f * NC];
        row[o] = tf32r(w);
#pragma unroll
        for (int k = 0; k < Kk; k++) {
            float m  = means[k * Ff + f];
            float lv = logvars[k * Ff + f];
            row[128 + k * Oo + o] = tf32r(m * w);
            row[768 + k * Oo + o] = tf32r(expf(lv) * w * w);
        }
    }
    if (idx < Kk * Ff) g_ivar[idx] = expf(-logvars[idx]);
}

__global__ void hist_kernel(const int* __restrict__ erow) {
    int e = blockIdx.x * blockDim.x + threadIdx.x;
    if (e < Ee) atomicAdd(&g_cnt[erow[e]], 1);
}

// single-block exclusive scan via warp shuffles (2 barriers); zeroes g_cnt after read
__global__ void scan_kernel() {
    const int t = threadIdx.x;          // 1024
    const int lane = t & 31, wid = t >> 5;
    const int CH = 10;                  // 1024*10 >= 10000
    int loc[CH];
    int sum = 0;
#pragma unroll
    for (int i = 0; i < CH; i++) {
        int idx = t * CH + i;
        int c = 0;
        if (idx < Nn) { c = g_cnt[idx]; g_cnt[idx] = 0; }
        loc[i] = sum; sum += c;
    }
    int inc = sum;
#pragma unroll
    for (int off = 1; off < 32; off <<= 1) {
        int v = __shfl_up_sync(0xffffffffu, inc, off);
        if (lane >= off) inc += v;
    }
    __shared__ int wsum[32];
    if (lane == 31) wsum[wid] = inc;
    __syncthreads();
    if (wid == 0) {
        int v = wsum[lane];
        int iv = v;
#pragma unroll
        for (int off = 1; off < 32; off <<= 1) {
            int u = __shfl_up_sync(0xffffffffu, iv, off);
            if (lane >= off) iv += u;
        }
        wsum[lane] = iv - v;            // exclusive warp prefix
    }
    __syncthreads();
    int base = wsum[wid] + inc - sum;   // exclusive prefix for this thread
#pragma unroll
    for (int i = 0; i < CH; i++) {
        int idx = t * CH + i;
        if (idx < Nn) g_rowptr[idx] = base + loc[i];
    }
    if (t == 1023) g_rowptr[Nn] = wsum[31] + inc;
}

__global__ void scatter_kernel(const int* __restrict__ erow,
                               const int* __restrict__ ecol,
                               const float* __restrict__ eval) {
    int e = blockIdx.x * blockDim.x + threadIdx.x;
    if (e < Ee) {
        int r = erow[e];
        int pos = g_rowptr[r] + atomicAdd(&g_fill[r], 1);
        g_scol[pos] = ecol[e];
        g_sval[pos] = eval[e];
    }
}

// Per node: expand xm / mask-bits, and gamma[k,n]
__global__ void mask_gamma_kernel(const float* __restrict__ x,
                                  const void* __restrict__ maskp,
                                  const float* __restrict__ means,
                                  const float* __restrict__ logp) {
    int n = blockIdx.x, t = threadIdx.x;   // 256 threads, t == feature
    int idx = n * Ff + t;
    float xv = x[idx];
    int mode = g_maskmode;
    int mm;
    if (mode == 0)      mm = (((const unsigned char*)maskp)[idx] != 0);
    else if (mode == 1) mm = (((const int*)maskp)[idx] != 0);
    else                mm = (((const float*)maskp)[idx] != 0.0f);

    g_xm[idx] = mm ? 0.0f : xv;
    int w = t >> 5, l = t & 31;
    unsigned bits = __ballot_sync(0xffffffffu, mm);
    if (l == 0) g_mkb[n * 8 + w] = bits;

    float q[Kk];
#pragma unroll
    for (int k = 0; k < Kk; k++) {
        float d = xv - means[k * Ff + t];
        q[k] = mm ? 0.0f : d * d * g_ivar[k * Ff + t];
    }
#pragma unroll
    for (int off = 16; off; off >>= 1)
#pragma unroll
        for (int k = 0; k < Kk; k++)
            q[k] += __shfl_down_sync(0xffffffffu, q[k], off);

    __shared__ float sq[8][Kk];
    if (l == 0)
#pragma unroll
        for (int k = 0; k < Kk; k++) sq[w][k] = q[k];
    __syncthreads();
    if (t == 0) {
        float logit[Kk];
#pragma unroll
        for (int k = 0; k < Kk; k++) {
            float s = 0.0f;
            for (int w2 = 0; w2 < 8; w2++) s += sq[w2][k];
            logit[k] = logp[k] - 0.5f * s;
        }
        float mx = logit[0];
#pragma unroll
        for (int k = 1; k < Kk; k++) mx = fmaxf(mx, logit[k]);
        float se = 0.0f, e[Kk];
#pragma unroll
        for (int k = 0; k < Kk; k++) { e[k] = expf(logit[k] - mx); se += e[k]; }
#pragma unroll
        for (int k = 0; k < Kk; k++) g_gamma[n * Kk + k] = e[k] / se;
    }
}

// CSR SPMM: Y = S@xm, M = S@mk, M2 = S2@mk, degw = rowsum(S). One block per row.
__global__ void spmm_kernel() {
    int n = blockIdx.x, t = threadIdx.x;   // 256 threads, t == feature
    int s = g_rowptr[n], e = g_rowptr[n + 1];
    const int w = t >> 5, l = t & 31;
    __shared__ int   sc[128];
    __shared__ float sv[128];
    float aY = 0.0f, aM = 0.0f, aM2 = 0.0f, dw = 0.0f;
    for (int base = s; base < e; base += 128) {
        int cnt = min(128, e - base);
        if (t < cnt) { sc[t] = g_scol[base + t]; sv[t] = g_sval[base + t]; }
        __syncthreads();
        for (int j = 0; j < cnt; j++) {
            int c = sc[j]; float v = sv[j];
            float xv = g_xm[c * Ff + t];
            float mv = (float)((g_mkb[c * 8 + w] >> l) & 1u);
            aY  += v * xv;
            aM  += v * mv;
            aM2 += v * v * mv;
            dw  += v;
        }
        __syncthreads();
    }
    int idx = n * Ff + t;
    g_Y [idx] = tf32r(aY);
    g_M [idx] = tf32r(aM);
    g_M2[idx] = tf32r(aM2);
    if (t == 0) g_degw[n] = dw;
}

// ---------------- tf32 mma.sync GEMM, cp.async double-buffered ----------------
#define AS_STRIDE 36
#define BS_STRIDE 132
#define AS_BUF (128 * AS_STRIDE)
#define BS_BUF (32 * BS_STRIDE)
#define GEMM_SMEM ((2 * AS_BUF + 2 * BS_BUF) * (int)sizeof(float))

__global__ __launch_bounds__(256) void gemm_kernel() {
    extern __shared__ float smem[];
    float* As = smem;                 // [2][128][36]
    float* Bs = smem + 2 * AS_BUF;    // [2][32][132]

    const int cb = blockIdx.x;   // 0..10
    const int rb = blockIdx.y;   // 0..78
    const float* __restrict__ A = (cb == 0) ? g_Y : ((cb < 6) ? g_M : g_M2);
    const float* __restrict__ B = g_Wall + cb * 128;

    const int tid  = threadIdx.x;
    const int lane = tid & 31, w = tid >> 5;
    const int wm = (w & 3) * 32;
    const int wn = (w >> 2) * 64;
    const int lr = lane >> 2, lc = lane & 3;
    const int rowbase = rb * 128;

    const int arow = tid >> 1;
    const int ahalf = (tid & 1) * 16;
    const int gr = rowbase + arow;
    const bool arow_ok = (gr < Nn);
    const float* Arow = A + (size_t)gr * Ff;
    const int brow = tid >> 3;
    const int bcol0 = (tid & 7) * 4;
    const float* Brow = B + (size_t)brow * NC;

    unsigned as_base = (unsigned)__cvta_generic_to_shared(As);
    unsigned bs_base = (unsigned)__cvta_generic_to_shared(Bs);

    float acc[2][8][4];
#pragma unroll
    for (int mt = 0; mt < 2; mt++)
#pragma unroll
        for (int nt = 0; nt < 8; nt++)
#pragma unroll
            for (int i = 0; i < 4; i++) acc[mt][nt][i] = 0.0f;

#define LOAD_TILE(KT, BUF) do {                                                     \
        unsigned adst = as_base + (unsigned)(((BUF) * AS_BUF + arow * AS_STRIDE + ahalf) * 4); \
        const float* asrc = Arow + (KT) + ahalf;                                    \
        _Pragma("unroll")                                                           \
        for (int j = 0; j < 4; j++)                                                 \
            cp_async16(adst + j * 16u, asrc + j * 4, arow_ok);                      \
        unsigned bdst = bs_base + (unsigned)(((BUF) * BS_BUF + brow * BS_STRIDE + bcol0) * 4); \
        const float* bsrc = Brow + (size_t)(KT) * NC + bcol0;                       \
        _Pragma("unroll")                                                           \
        for (int j = 0; j < 4; j++)                                                 \
            cp_async16(bdst + j * 128u, bsrc + j * 32, true);                       \
    } while (0)

    LOAD_TILE(0, 0);
    cp_async_commit();

    for (int kt = 0; kt < 8; kt++) {
        if (kt < 7) {
            LOAD_TILE((kt + 1) * 32, (kt + 1) & 1);
            cp_async_commit();
            cp_async_wait<1>();
        } else {
            cp_async_wait<0>();
        }
        __syncthreads();

        const float* Ab = As + (kt & 1) * AS_BUF;
        const float* Bb = Bs + (kt & 1) * BS_BUF;
#pragma unroll
        for (int ks = 0; ks < 4; ks++) {
            const int kb = ks * 8;
            unsigned a[2][4], b[8][2];
#pragma unroll
            for (int mt = 0; mt < 2; mt++) {
                int mr = wm + mt * 16 + lr;
                a[mt][0] = __float_as_uint(Ab[ mr      * AS_STRIDE + kb + lc    ]);
                a[mt][1] = __float_as_uint(Ab[(mr + 8) * AS_STRIDE + kb + lc    ]);
                a[mt][2] = __float_as_uint(Ab[ mr      * AS_STRIDE + kb + lc + 4]);
                a[mt][3] = __float_as_uint(Ab[(mr + 8) * AS_STRIDE + kb + lc + 4]);
            }
#pragma unroll
            for (int nt = 0; nt < 8; nt++) {
                int nc2 = wn + nt * 8 + lr;
                b[nt][0] = __float_as_uint(Bb[(kb + lc    ) * BS_STRIDE + nc2]);
                b[nt][1] = __float_as_uint(Bb[(kb + lc + 4) * BS_STRIDE + nc2]);
            }
#pragma unroll
            for (int mt = 0; mt < 2; mt++)
#pragma unroll
                for (int nt = 0; nt < 8; nt++) {
                    asm volatile(
                        "mma.sync.aligned.m16n8k8.row.col.f32.tf32.tf32.f32 "
                        "{%0,%1,%2,%3}, {%4,%5,%6,%7}, {%8,%9}, {%0,%1,%2,%3};"
                        : "+f"(acc[mt][nt][0]), "+f"(acc[mt][nt][1]),
                          "+f"(acc[mt][nt][2]), "+f"(acc[mt][nt][3])
                        : "r"(a[mt][0]), "r"(a[mt][1]), "r"(a[mt][2]), "r"(a[mt][3]),
                          "r"(b[nt][0]), "r"(b[nt][1]));
                }
        }
        __syncthreads();
    }
#undef LOAD_TILE

#pragma unroll
    for (int mt = 0; mt < 2; mt++) {
        int r0 = rowbase + wm + mt * 16 + lr;
#pragma unroll
        for (int nt = 0; nt < 8; nt++) {
            int col = cb * 128 + wn + nt * 8 + lc * 2;
            if (r0 < Nn)
                *(float2*)&g_D[(size_t)r0 * NC + col] =
                    make_float2(acc[mt][nt][0], acc[mt][nt][1]);
            if (r0 + 8 < Nn)
                *(float2*)&g_D[(size_t)(r0 + 8) * NC + col] =
                    make_float2(acc[mt][nt][2], acc[mt][nt][3]);
        }
    }
}

// ex_relu + gamma-weighted sum; also resets g_fill[n] for next call
__global__ void final_kernel(const float* __restrict__ bias, float* __restrict__ out) {
    int n = blockIdx.x, o = threadIdx.x;   // 128 threads
    if (o == 0) g_fill[n] = 0;
    const float* Dn = &g_D[(size_t)n * NC];
    float d0 = Dn[o];
    float dw = g_degw[n];
    float bo = bias[o];
    float acc = 0.0f;
#pragma unroll
    for (int k = 0; k < Kk; k++) {
        float cx = d0 + Dn[128 + k * 128 + o] + dw * bo;
        float cc = Dn[768 + k * 128 + o];
        float ex;
        if (cc == 0.0f) {
            ex = fmaxf(cx, 0.0f);
        } else {
            float sq = sqrtf(cc);
            float w  = cx / sq;
            ex = sq * (0.3989422804014327f * expf(-0.5f * w * w)
                       + 0.5f * w * (1.0f + erff(w * 0.70710678118654752f)));
        }
        acc += g_gamma[n * Kk + k] * ex;
    }
    out[n * Oo + o] = acc;
}

extern "C" void kernel_launch(void* const* d_in, const int* in_sizes, int n_in,
                              void* d_out, int out_size) {
    const float* x_vals  = (const float*)d_in[0];
    const void*  x_mask  = (const void*) d_in[1];
    const int*   erow    = (const int*)  d_in[2];
    const int*   ecol    = (const int*)  d_in[3];
    const float* eval    = (const float*)d_in[4];
    const float* logp    = (const float*)d_in[5];
    const float* means   = (const float*)d_in[6];
    const float* logvars = (const float*)d_in[7];
    const float* weight  = (const float*)d_in[8];
    const float* bias    = (const float*)d_in[9];
    float* out = (float*)d_out;
    (void)in_sizes; (void)n_in; (void)out_size;

    static cudaStream_t s2 = 0;
    static cudaEvent_t evFork = 0, evJoin = 0;
    if (!s2) {
        cudaFuncSetAttribute(gemm_kernel, cudaFuncAttributeMaxDynamicSharedMemorySize, GEMM_SMEM);
        cudaStreamCreateWithFlags(&s2, cudaStreamNonBlocking);
        cudaEventCreateWithFlags(&evFork, cudaEventDisableTiming);
        cudaEventCreateWithFlags(&evJoin, cudaEventDisableTiming);
    }

    // fork: side stream does mask/weights prep while main stream builds CSR
    cudaEventRecord(evFork, 0);
    cudaStreamWaitEvent(s2, evFork, 0);

    detect_mask_kernel<<<1, 256, 0, s2>>>((const unsigned int*)x_mask);
    prep_weights_kernel<<<(Ff * Oo + 255) / 256, 256, 0, s2>>>(weight, means, logvars);
    mask_gamma_kernel<<<Nn, 256, 0, s2>>>(x_vals, x_mask, means, logp);
    cudaEventRecord(evJoin, s2);

    hist_kernel<<<(Ee + 255) / 256, 256>>>(erow);
    scan_kernel<<<1, 1024>>>();
    scatter_kernel<<<(Ee + 255) / 256, 256>>>(erow, ecol, eval);

    cudaStreamWaitEvent(0, evJoin, 0);

    spmm_kernel<<<Nn, 256>>>();
    dim3 gg(11, 79);
    gemm_kernel<<<gg, 256, GEMM_SMEM>>>();
    final_kernel<<<Nn, 128>>>(bias, out);
}

// round 6
// speedup vs baseline: 2.1690x; 1.2150x over previous
#include <cuda_runtime.h>
#include <cuda_fp16.h>
#include <math.h>

#define Nn 10000
#define Ff 256
#define Oo 128
#define Kk 5
#define Ee 160000
#define NC 1408   /* 128 (Y@W) + 5*128 (M@Wk) + 5*128 (M2@Vk) */

// ---------------- scratch ----------------
__device__ float g_xm[Nn * Ff];
__device__ unsigned g_mkb[Nn * 8];      // bit-packed mask, 256 bits per row
__device__ __half g_Y [Nn * Ff];
__device__ __half g_M [Nn * Ff];
__device__ __half g_M2[Nn * Ff];
__device__ float g_gamma[Nn * Kk];
__device__ float g_degw[Nn];
__device__ __half g_WallT[NC * Ff];     // transposed: [out_col][feature], K-contiguous
__device__ float g_ivar[Kk * Ff];
__device__ float g_D[Nn * NC];
__device__ int   g_cnt[Nn];             // zero at entry; re-zeroed by scan_kernel
__device__ int   g_fill[Nn];            // zero at entry; re-zeroed by final_kernel
__device__ int   g_rowptr[Nn + 1];
__device__ int   g_scol[Ee];
__device__ float g_sval[Ee];
__device__ int   g_maskmode;

__device__ __forceinline__ void cp_async16(unsigned smem_addr, const void* gptr, bool pred) {
    int bytes = pred ? 16 : 0;
    asm volatile("cp.async.cg.shared.global [%0], [%1], 16, %2;\n"
                 :: "r"(smem_addr), "l"(gptr), "r"(bytes));
}
__device__ __forceinline__ void cp_async_commit() {
    asm volatile("cp.async.commit_group;\n");
}
template<int N> __device__ __forceinline__ void cp_async_wait() {
    asm volatile("cp.async.wait_group %0;\n" :: "n"(N));
}

// ---------------- mask dtype detection ----------------
__global__ void detect_mask_kernel(const unsigned int* m) {
    int t = threadIdx.x;
    int i32ok = 1, f32ok = 1;
    for (int i = t; i < 1024; i += 256) {
        unsigned v = m[i];
        if (v > 1u) i32ok = 0;
        if (!(v == 0u || v == 0x3F800000u)) f32ok = 0;
    }
    int allI = __syncthreads_and(i32ok);
    int allF = __syncthreads_and(f32ok);
    if (t == 0) g_maskmode = allI ? 1 : (allF ? 2 : 0);
}

// Build g_WallT[o'][f] in fp16. Block = output column o' (0..NC-1), thread = f.
// cb = o'>>7: 0 -> W[f][o]; 1..5 -> means[k][f]*W; 6..10 -> exp(lv[k][f])*W^2.
// Blocks 0..4 additionally write g_ivar[b*256+f].
__global__ void prep_weights_kernel(const float* __restrict__ W,
                                    const float* __restrict__ means,
                                    const float* __restrict__ logvars) {
    int op = blockIdx.x;          // 0..1407
    int f  = threadIdx.x;         // 0..255
    int cb = op >> 7, o = op & 127;
    float w = W[f * Oo + o];
    float val;
    if (cb == 0) {
        val = w;
    } else if (cb < 6) {
        int k = cb - 1;
        val = means[k * Ff + f] * w;
    } else {
        int k = cb - 6;
        val = expf(logvars[k * Ff + f]) * w * w;
    }
    g_WallT[op * Ff + f] = __float2half_rn(val);
    if (op < Kk) g_ivar[op * Ff + f] = expf(-logvars[op * Ff + f]);
}

__global__ void hist_kernel(const int* __restrict__ erow) {
    int e = blockIdx.x * blockDim.x + threadIdx.x;
    if (e < Ee) atomicAdd(&g_cnt[erow[e]], 1);
}

// single-block exclusive scan via warp shuffles; zeroes g_cnt after read
__global__ void scan_kernel() {
    const int t = threadIdx.x;          // 1024
    const int lane = t & 31, wid = t >> 5;
    const int CH = 10;
    int loc[CH];
    int sum = 0;
#pragma unroll
    for (int i = 0; i < CH; i++) {
        int idx = t * CH + i;
        int c = 0;
        if (idx < Nn) { c = g_cnt[idx]; g_cnt[idx] = 0; }
        loc[i] = sum; sum += c;
    }
    int inc = sum;
#pragma unroll
    for (int off = 1; off < 32; off <<= 1) {
        int v = __shfl_up_sync(0xffffffffu, inc, off);
        if (lane >= off) inc += v;
    }
    __shared__ int wsum[32];
    if (lane == 31) wsum[wid] = inc;
    __syncthreads();
    if (wid == 0) {
        int v = wsum[lane];
        int iv = v;
#pragma unroll
        for (int off = 1; off < 32; off <<= 1) {
            int u = __shfl_up_sync(0xffffffffu, iv, off);
            if (lane >= off) iv += u;
        }
        wsum[lane] = iv - v;
    }
    __syncthreads();
    int base = wsum[wid] + inc - sum;
#pragma unroll
    for (int i = 0; i < CH; i++) {
        int idx = t * CH + i;
        if (idx < Nn) g_rowptr[idx] = base + loc[i];
    }
    if (t == 1023) g_rowptr[Nn] = wsum[31] + inc;
}

__global__ void scatter_kernel(const int* __restrict__ erow,
                               const int* __restrict__ ecol,
                               const float* __restrict__ eval) {
    int e = blockIdx.x * blockDim.x + threadIdx.x;
    if (e < Ee) {
        int r = erow[e];
        int pos = g_rowptr[r] + atomicAdd(&g_fill[r], 1);
        g_scol[pos] = ecol[e];
        g_sval[pos] = eval[e];
    }
}

// Per node: expand xm / mask-bits, and gamma[k,n]
__global__ void mask_gamma_kernel(const float* __restrict__ x,
                                  const void* __restrict__ maskp,
                                  const float* __restrict__ means,
                                  const float* __restrict__ logp) {
    int n = blockIdx.x, t = threadIdx.x;   // 256 threads, t == feature
    int idx = n * Ff + t;
    float xv = x[idx];
    int mode = g_maskmode;
    int mm;
    if (mode == 0)      mm = (((const unsigned char*)maskp)[idx] != 0);
    else if (mode == 1) mm = (((const int*)maskp)[idx] != 0);
    else                mm = (((const float*)maskp)[idx] != 0.0f);

    g_xm[idx] = mm ? 0.0f : xv;
    int w = t >> 5, l = t & 31;
    unsigned bits = __ballot_sync(0xffffffffu, mm);
    if (l == 0) g_mkb[n * 8 + w] = bits;

    float q[Kk];
#pragma unroll
    for (int k = 0; k < Kk; k++) {
        float d = xv - means[k * Ff + t];
        q[k] = mm ? 0.0f : d * d * g_ivar[k * Ff + t];
    }
#pragma unroll
    for (int off = 16; off; off >>= 1)
#pragma unroll
        for (int k = 0; k < Kk; k++)
            q[k] += __shfl_down_sync(0xffffffffu, q[k], off);

    __shared__ float sq[8][Kk];
    if (l == 0)
#pragma unroll
        for (int k = 0; k < Kk; k++) sq[w][k] = q[k];
    __syncthreads();
    if (t == 0) {
        float logit[Kk];
#pragma unroll
        for (int k = 0; k < Kk; k++) {
            float s = 0.0f;
            for (int w2 = 0; w2 < 8; w2++) s += sq[w2][k];
            logit[k] = logp[k] - 0.5f * s;
        }
        float mx = logit[0];
#pragma unroll
        for (int k = 1; k < Kk; k++) mx = fmaxf(mx, logit[k]);
        float se = 0.0f, e[Kk];
#pragma unroll
        for (int k = 0; k < Kk; k++) { e[k] = expf(logit[k] - mx); se += e[k]; }
#pragma unroll
        for (int k = 0; k < Kk; k++) g_gamma[n * Kk + k] = e[k] / se;
    }
}

// CSR SPMM: Y = S@xm, M = S@mk, M2 = S2@mk, degw = rowsum(S). One block per row.
// Outputs fp16 (feed the fp16 tensor-core GEMM; 10-bit mantissa = tf32-equivalent).
__global__ void spmm_kernel() {
    int n = blockIdx.x, t = threadIdx.x;   // 256 threads, t == feature
    int s = g_rowptr[n], e = g_rowptr[n + 1];
    const int w = t >> 5, l = t & 31;
    __shared__ int   sc[128];
    __shared__ float sv[128];
    float aY = 0.0f, aM = 0.0f, aM2 = 0.0f, dw = 0.0f;
    for (int base = s; base < e; base += 128) {
        int cnt = min(128, e - base);
        if (t < cnt) { sc[t] = g_scol[base + t]; sv[t] = g_sval[base + t]; }
        __syncthreads();
        for (int j = 0; j < cnt; j++) {
            int c = sc[j]; float v = sv[j];
            float xv = g_xm[c * Ff + t];
            float mv = (float)((g_mkb[c * 8 + w] >> l) & 1u);
            aY  += v * xv;
            aM  += v * mv;
            aM2 += v * v * mv;
            dw  += v;
        }
        __syncthreads();
    }
    int idx = n * Ff + t;
    g_Y [idx] = __float2half_rn(aY);
    g_M [idx] = __float2half_rn(aM);
    g_M2[idx] = __float2half_rn(aM2);
    if (t == 0) g_degw[n] = dw;
}

// ---------------- fp16 mma.sync GEMM (m16n8k16), cp.async double-buffered ----------------
// D[n, cb*128 + j] = Asrc @ WallT_block^T.  Asrc: cb==0 -> Y ; 1..5 -> M ; 6..10 -> M2
// BM=128, BN=128, BK=32, 8 warps (4 M x 2 N), warp tile 32x64.
// Tiles stored [row][40 halves] (pad 8): frag LDS conflict-free (20 words/row).
#define TS 40                       /* halves per smem row */
#define TILE_HALVES (128 * TS)      /* per buffer per matrix */

__global__ __launch_bounds__(256) void gemm_kernel() {
    __shared__ __half As[2][128][TS];
    __shared__ __half Bs[2][128][TS];

    const int cb = blockIdx.x;   // 0..10
    const int rb = blockIdx.y;   // 0..78
    const __half* __restrict__ A = (cb == 0) ? g_Y : ((cb < 6) ? g_M : g_M2);
    const __half* __restrict__ B = g_WallT + (size_t)cb * 128 * Ff;

    const int tid  = threadIdx.x;
    const int lane = tid & 31, w = tid >> 5;
    const int wm = (w & 3) * 32;
    const int wn = (w >> 2) * 64;
    const int lr = lane >> 2, lc = lane & 3;
    const int rowbase = rb * 128;

    // loader: thread -> row = tid>>1 (0..127), half-row = tid&1 (2 x 16B chunks)
    const int ldrow = tid >> 1;
    const int ldoff = (tid & 1) * 16;       // half offset within 32-half row
    const int gr = rowbase + ldrow;
    const bool arow_ok = (gr < Nn);
    const __half* Arow = A + (size_t)gr * Ff;
    const __half* Brow = B + (size_t)ldrow * Ff;

    unsigned as_base = (unsigned)__cvta_generic_to_shared(&As[0][0][0]);
    unsigned bs_base = (unsigned)__cvta_generic_to_shared(&Bs[0][0][0]);

    float acc[2][8][4];
#pragma unroll
    for (int mt = 0; mt < 2; mt++)
#pragma unroll
        for (int nt = 0; nt < 8; nt++)
#pragma unroll
            for (int i = 0; i < 4; i++) acc[mt][nt][i] = 0.0f;

#define LOAD_TILE(KT, BUF) do {                                                           \
        unsigned adst = as_base + (unsigned)(((BUF) * TILE_HALVES + ldrow * TS + ldoff) * 2); \
        const __half* asrc = Arow + (KT) + ldoff;                                         \
        cp_async16(adst,       asrc,     arow_ok);                                        \
        cp_async16(adst + 16u, asrc + 8, arow_ok);                                        \
        unsigned bdst = bs_base + (unsigned)(((BUF) * TILE_HALVES + ldrow * TS + ldoff) * 2); \
        const __half* bsrc = Brow + (KT) + ldoff;                                         \
        cp_async16(bdst,       bsrc,     true);                                           \
        cp_async16(bdst + 16u, bsrc + 8, true);                                           \
    } while (0)

    LOAD_TILE(0, 0);
    cp_async_commit();

    for (int kt = 0; kt < 8; kt++) {
        if (kt < 7) {
            LOAD_TILE((kt + 1) * 32, (kt + 1) & 1);
            cp_async_commit();
            cp_async_wait<1>();
        } else {
            cp_async_wait<0>();
        }
        __syncthreads();

        const __half (*Ab)[TS] = As[kt & 1];
        const __half (*Bb)[TS] = Bs[kt & 1];
#pragma unroll
        for (int ks = 0; ks < 2; ks++) {
            const int kb = ks * 16;           // half offset of this k16 step
            unsigned a[2][4], b[8][2];
#pragma unroll
            for (int mt = 0; mt < 2; mt++) {
                int mr = wm + mt * 16 + lr;
                a[mt][0] = *(const unsigned*)&Ab[mr    ][kb + 2 * lc    ];
                a[mt][1] = *(const unsigned*)&Ab[mr + 8][kb + 2 * lc    ];
                a[mt][2] = *(const unsigned*)&Ab[mr    ][kb + 2 * lc + 8];
                a[mt][3] = *(const unsigned*)&Ab[mr + 8][kb + 2 * lc + 8];
            }
#pragma unroll
            for (int nt = 0; nt < 8; nt++) {
                int nr = wn + nt * 8 + lr;
                b[nt][0] = *(const unsigned*)&Bb[nr][kb + 2 * lc    ];
                b[nt][1] = *(const unsigned*)&Bb[nr][kb + 2 * lc + 8];
            }
#pragma unroll
            for (int mt = 0; mt < 2; mt++)
#pragma unroll
                for (int nt = 0; nt < 8; nt++) {
                    asm volatile(
                        "mma.sync.aligned.m16n8k16.row.col.f32.f16.f16.f32 "
                        "{%0,%1,%2,%3}, {%4,%5,%6,%7}, {%8,%9}, {%0,%1,%2,%3};"
                        : "+f"(acc[mt][nt][0]), "+f"(acc[mt][nt][1]),
                          "+f"(acc[mt][nt][2]), "+f"(acc[mt][nt][3])
                        : "r"(a[mt][0]), "r"(a[mt][1]), "r"(a[mt][2]), "r"(a[mt][3]),
                          "r"(b[nt][0]), "r"(b[nt][1]));
                }
        }
        __syncthreads();
    }
#undef LOAD_TILE

#pragma unroll
    for (int mt = 0; mt < 2; mt++) {
        int r0 = rowbase + wm + mt * 16 + lr;
#pragma unroll
        for (int nt = 0; nt < 8; nt++) {
            int col = cb * 128 + wn + nt * 8 + lc * 2;
            if (r0 < Nn)
                *(float2*)&g_D[(size_t)r0 * NC + col] =
                    make_float2(acc[mt][nt][0], acc[mt][nt][1]);
            if (r0 + 8 < Nn)
                *(float2*)&g_D[(size_t)(r0 + 8) * NC + col] =
                    make_float2(acc[mt][nt][2], acc[mt][nt][3]);
        }
    }
}

// ex_relu + gamma-weighted sum; also resets g_fill[n] for next call
__global__ void final_kernel(const float* __restrict__ bias, float* __restrict__ out) {
    int n = blockIdx.x, o = threadIdx.x;   // 128 threads
    if (o == 0) g_fill[n] = 0;
    const float* Dn = &g_D[(size_t)n * NC];
    float d0 = Dn[o];
    float dw = g_degw[n];
    float bo = bias[o];
    float acc = 0.0f;
#pragma unroll
    for (int k = 0; k < Kk; k++) {
        float cx = d0 + Dn[128 + k * 128 + o] + dw * bo;
        float cc = Dn[768 + k * 128 + o];
        float ex;
        if (cc == 0.0f) {
            ex = fmaxf(cx, 0.0f);
        } else {
            float sq = sqrtf(cc);
            float w  = cx / sq;
            ex = sq * (0.3989422804014327f * expf(-0.5f * w * w)
                       + 0.5f * w * (1.0f + erff(w * 0.70710678118654752f)));
        }
        acc += g_gamma[n * Kk + k] * ex;
    }
    out[n * Oo + o] = acc;
}

extern "C" void kernel_launch(void* const* d_in, const int* in_sizes, int n_in,
                              void* d_out, int out_size) {
    const float* x_vals  = (const float*)d_in[0];
    const void*  x_mask  = (const void*) d_in[1];
    const int*   erow    = (const int*)  d_in[2];
    const int*   ecol    = (const int*)  d_in[3];
    const float* eval    = (const float*)d_in[4];
    const float* logp    = (const float*)d_in[5];
    const float* means   = (const float*)d_in[6];
    const float* logvars = (const float*)d_in[7];
    const float* weight  = (const float*)d_in[8];
    const float* bias    = (const float*)d_in[9];
    float* out = (float*)d_out;
    (void)in_sizes; (void)n_in; (void)out_size;

    static cudaStream_t s2 = 0;
    static cudaEvent_t evFork = 0, evJoin = 0;
    if (!s2) {
        cudaStreamCreateWithFlags(&s2, cudaStreamNonBlocking);
        cudaEventCreateWithFlags(&evFork, cudaEventDisableTiming);
        cudaEventCreateWithFlags(&evJoin, cudaEventDisableTiming);
    }

    // fork: side stream does mask/weights prep while main stream builds CSR
    cudaEventRecord(evFork, 0);
    cudaStreamWaitEvent(s2, evFork, 0);

    detect_mask_kernel<<<1, 256, 0, s2>>>((const unsigned int*)x_mask);
    prep_weights_kernel<<<NC, 256, 0, s2>>>(weight, means, logvars);
    mask_gamma_kernel<<<Nn, 256, 0, s2>>>(x_vals, x_mask, means, logp);
    cudaEventRecord(evJoin, s2);

    hist_kernel<<<(Ee + 255) / 256, 256>>>(erow);
    scan_kernel<<<1, 1024>>>();
    scatter_kernel<<<(Ee + 255) / 256, 256>>>(erow, ecol, eval);

    cudaStreamWaitEvent(0, evJoin, 0);

    spmm_kernel<<<Nn, 256>>>();
    dim3 gg(11, 79);
    gemm_kernel<<<gg, 256>>>();
    final_kernel<<<Nn, 128>>>(bias, out);
}

// round 7
// speedup vs baseline: 2.1875x; 1.0085x over previous
#include <cuda_runtime.h>
#include <cuda_fp16.h>
#include <math.h>

#define Nn 10000
#define Ff 256
#define Oo 128
#define Kk 5
#define Ee 160000
#define NC 1408

// ---------------- scratch ----------------
__device__ __half g_xmh[Nn * Ff];
__device__ unsigned g_mkb[Nn * 8];
__device__ __half g_Y [Nn * Ff];
__device__ __half g_M [Nn * Ff];
__device__ __half g_M2[Nn * Ff];
__device__ float g_gamma[Nn * Kk];
__device__ float g_degw[Nn];
__device__ __half g_WallT[NC * Ff];     // [out_col][feature], K-contiguous
__device__ float g_ivar[Kk * Ff];
__device__ int   g_cnt[Nn];             // zero at entry; re-zeroed by scan_kernel
__device__ int   g_fill[Nn];            // zero at entry; re-zeroed by fused epilogue
__device__ int   g_rowptr[Nn + 1];
__device__ int   g_scol[Ee];
__device__ float g_sval[Ee];
__device__ int   g_maskmode;

__device__ __forceinline__ void cp_async16(unsigned smem_addr, const void* gptr, bool pred) {
    int bytes = pred ? 16 : 0;
    asm volatile("cp.async.cg.shared.global [%0], [%1], 16, %2;\n"
                 :: "r"(smem_addr), "l"(gptr), "r"(bytes));
}
__device__ __forceinline__ void cp_async_commit() {
    asm volatile("cp.async.commit_group;\n");
}
template<int N> __device__ __forceinline__ void cp_async_wait() {
    asm volatile("cp.async.wait_group %0;\n" :: "n"(N));
}

__device__ __forceinline__ float ex_relu(float cx, float cc) {
    if (cc == 0.0f) return fmaxf(cx, 0.0f);
    float sq = sqrtf(cc);
    float w  = cx / sq;
    return sq * (0.3989422804014327f * expf(-0.5f * w * w)
                 + 0.5f * w * (1.0f + erff(w * 0.70710678118654752f)));
}

// ---------------- mask dtype detection ----------------
__global__ void detect_mask_kernel(const unsigned int* m) {
    int t = threadIdx.x;
    int i32ok = 1, f32ok = 1;
    for (int i = t; i < 1024; i += 256) {
        unsigned v = m[i];
        if (v > 1u) i32ok = 0;
        if (!(v == 0u || v == 0x3F800000u)) f32ok = 0;
    }
    int allI = __syncthreads_and(i32ok);
    int allF = __syncthreads_and(f32ok);
    if (t == 0) g_maskmode = allI ? 1 : (allF ? 2 : 0);
}

// Build g_WallT[o'][f] fp16. Block = out col o', thread = f.
__global__ void prep_weights_kernel(const float* __restrict__ W,
                                    const float* __restrict__ means,
                                    const float* __restrict__ logvars) {
    int op = blockIdx.x;          // 0..1407
    int f  = threadIdx.x;         // 0..255
    int cb = op >> 7, o = op & 127;
    float w = W[f * Oo + o];
    float val;
    if (cb == 0)       val = w;
    else if (cb < 6)   val = means[(cb - 1) * Ff + f] * w;
    else               val = expf(logvars[(cb - 6) * Ff + f]) * w * w;
    g_WallT[op * Ff + f] = __float2half_rn(val);
    if (op < Kk) g_ivar[op * Ff + f] = expf(-logvars[op * Ff + f]);
}

__global__ void hist_kernel(const int* __restrict__ erow) {
    int e = blockIdx.x * blockDim.x + threadIdx.x;
    if (e < Ee) atomicAdd(&g_cnt[erow[e]], 1);
}

// warp-shuffle exclusive scan; zeroes g_cnt after read
__global__ void scan_kernel() {
    const int t = threadIdx.x;          // 1024
    const int lane = t & 31, wid = t >> 5;
    const int CH = 10;
    int loc[CH];
    int sum = 0;
#pragma unroll
    for (int i = 0; i < CH; i++) {
        int idx = t * CH + i;
        int c = 0;
        if (idx < Nn) { c = g_cnt[idx]; g_cnt[idx] = 0; }
        loc[i] = sum; sum += c;
    }
    int inc = sum;
#pragma unroll
    for (int off = 1; off < 32; off <<= 1) {
        int v = __shfl_up_sync(0xffffffffu, inc, off);
        if (lane >= off) inc += v;
    }
    __shared__ int wsum[32];
    if (lane == 31) wsum[wid] = inc;
    __syncthreads();
    if (wid == 0) {
        int v = wsum[lane];
        int iv = v;
#pragma unroll
        for (int off = 1; off < 32; off <<= 1) {
            int u = __shfl_up_sync(0xffffffffu, iv, off);
            if (lane >= off) iv += u;
        }
        wsum[lane] = iv - v;
    }
    __syncthreads();
    int base = wsum[wid] + inc - sum;
#pragma unroll
    for (int i = 0; i < CH; i++) {
        int idx = t * CH + i;
        if (idx < Nn) g_rowptr[idx] = base + loc[i];
    }
    if (t == 1023) g_rowptr[Nn] = wsum[31] + inc;
}

__global__ void scatter_kernel(const int* __restrict__ erow,
                               const int* __restrict__ ecol,
                               const float* __restrict__ eval) {
    int e = blockIdx.x * blockDim.x + threadIdx.x;
    if (e < Ee) {
        int r = erow[e];
        int pos = g_rowptr[r] + atomicAdd(&g_fill[r], 1);
        g_scol[pos] = ecol[e];
        g_sval[pos] = eval[e];
    }
}

// Per node: xm (fp16) / mask-bits / gamma
__global__ void mask_gamma_kernel(const float* __restrict__ x,
                                  const void* __restrict__ maskp,
                                  const float* __restrict__ means,
                                  const float* __restrict__ logp) {
    int n = blockIdx.x, t = threadIdx.x;   // 256 threads
    int idx = n * Ff + t;
    float xv = x[idx];
    int mode = g_maskmode;
    int mm;
    if (mode == 0)      mm = (((const unsigned char*)maskp)[idx] != 0);
    else if (mode == 1) mm = (((const int*)maskp)[idx] != 0);
    else                mm = (((const float*)maskp)[idx] != 0.0f);

    g_xmh[idx] = __float2half_rn(mm ? 0.0f : xv);
    int w = t >> 5, l = t & 31;
    unsigned bits = __ballot_sync(0xffffffffu, mm);
    if (l == 0) g_mkb[n * 8 + w] = bits;

    float q[Kk];
#pragma unroll
    for (int k = 0; k < Kk; k++) {
        float d = xv - means[k * Ff + t];
        q[k] = mm ? 0.0f : d * d * g_ivar[k * Ff + t];
    }
#pragma unroll
    for (int off = 16; off; off >>= 1)
#pragma unroll
        for (int k = 0; k < Kk; k++)
            q[k] += __shfl_down_sync(0xffffffffu, q[k], off);

    __shared__ float sq[8][Kk];
    if (l == 0)
#pragma unroll
        for (int k = 0; k < Kk; k++) sq[w][k] = q[k];
    __syncthreads();
    if (t == 0) {
        float logit[Kk];
#pragma unroll
        for (int k = 0; k < Kk; k++) {
            float s = 0.0f;
            for (int w2 = 0; w2 < 8; w2++) s += sq[w2][k];
            logit[k] = logp[k] - 0.5f * s;
        }
        float mx = logit[0];
#pragma unroll
        for (int k = 1; k < Kk; k++) mx = fmaxf(mx, logit[k]);
        float se = 0.0f, e[Kk];
#pragma unroll
        for (int k = 0; k < Kk; k++) { e[k] = expf(logit[k] - mx); se += e[k]; }
#pragma unroll
        for (int k = 0; k < Kk; k++) g_gamma[n * Kk + k] = e[k] / se;
    }
}

// CSR SPMM with fp16 gather
__global__ void spmm_kernel() {
    int n = blockIdx.x, t = threadIdx.x;   // 256 threads
    int s = g_rowptr[n], e = g_rowptr[n + 1];
    const int w = t >> 5, l = t & 31;
    __shared__ int   sc[128];
    __shared__ float sv[128];
    float aY = 0.0f, aM = 0.0f, aM2 = 0.0f, dw = 0.0f;
    for (int base = s; base < e; base += 128) {
        int cnt = min(128, e - base);
        if (t < cnt) { sc[t] = g_scol[base + t]; sv[t] = g_sval[base + t]; }
        __syncthreads();
        for (int j = 0; j < cnt; j++) {
            int c = sc[j]; float v = sv[j];
            float xv = __half2float(g_xmh[c * Ff + t]);
            float mv = (float)((g_mkb[c * 8 + w] >> l) & 1u);
            aY  += v * xv;
            aM  += v * mv;
            aM2 += v * v * mv;
            dw  += v;
        }
        __syncthreads();
    }
    int idx = n * Ff + t;
    g_Y [idx] = __float2half_rn(aY);
    g_M [idx] = __float2half_rn(aM);
    g_M2[idx] = __float2half_rn(aM2);
    if (t == 0) g_degw[n] = dw;
}

// ---------------- fused GEMM (11 panels) + ex_relu + gamma reduction ----------------
// Block: 64 rows x 32 out-cols. 8 warps: rw = wid&3 (16-row band), cw = wid>>2 (16-col band).
// All 11 panels accumulated simultaneously; epilogue consumes cx/cc from registers.
#define TSH 40                         /* halves per smem row (20 words: conflict-free frags) */
#define A_BUFH (3 * 64 * TSH)          /* halves per A buffer (Y,M,M2) */
#define B_BUFH (352 * TSH)             /* halves per B buffer (11 panels x 32 rows) */
#define FUSED_SMEM ((2 * (A_BUFH + B_BUFH)) * 2)

__global__ __launch_bounds__(256) void fused_kernel(const float* __restrict__ bias,
                                                    float* __restrict__ out) {
    extern __shared__ __half sm[];
    // layout: As[2][3][64][TSH] | Bs[2][352][TSH]
    __half* Bsm = sm + 2 * A_BUFH;

    const int q  = blockIdx.x;   // 0..3  (32-col band)
    const int rb = blockIdx.y;   // 0..156 (64-row band)
    const int tid  = threadIdx.x;
    const int lane = tid & 31, wid = tid >> 5;
    const int rw = wid & 3, cw = wid >> 2;
    const int lr = lane >> 2, lc = lane & 3;
    const int rowbase = rb * 64;

    if (q == 0 && tid < 64 && rowbase + tid < Nn) g_fill[rowbase + tid] = 0;

    unsigned as_base = (unsigned)__cvta_generic_to_shared(sm);
    unsigned bs_base = (unsigned)__cvta_generic_to_shared(Bsm);

    const __half* Amats[3] = { g_Y, g_M, g_M2 };

    float acc[11][2][4];
#pragma unroll
    for (int p = 0; p < 11; p++)
#pragma unroll
        for (int nt = 0; nt < 2; nt++)
#pragma unroll
            for (int i = 0; i < 4; i++) acc[p][nt][i] = 0.0f;

    // A loader: 768 chunks of 16B per buffer (3 mats x 64 rows x 4 chunks)
    // B loader: 1408 chunks (352 rows x 4 chunks)
#define LOAD_TILE(KT, BUF) do {                                                        \
        _Pragma("unroll")                                                              \
        for (int i = 0; i < 3; i++) {                                                  \
            int c = tid + i * 256;                                                     \
            int mat = c >> 8, rr = (c >> 2) & 63, off = (c & 3) * 8;                   \
            int grow = rowbase + rr;                                                   \
            unsigned dst = as_base + (unsigned)((((BUF) * 3 + mat) * 64 + rr) * TSH + off) * 2u; \
            cp_async16(dst, Amats[mat] + (size_t)grow * Ff + (KT) + off, grow < Nn);   \
        }                                                                              \
        _Pragma("unroll")                                                              \
        for (int i = 0; i < 6; i++) {                                                  \
            int c = tid + i * 256;                                                     \
            if (c < 1408) {                                                            \
                int brow = c >> 2, off = (c & 3) * 8;                                  \
                int panel = brow >> 5, rip = brow & 31;                                \
                unsigned dst = bs_base + (unsigned)(((BUF) * 352 + brow) * TSH + off) * 2u; \
                cp_async16(dst, g_WallT + (size_t)(panel * 128 + q * 32 + rip) * Ff + (KT) + off, true); \
            }                                                                          \
        }                                                                              \
    } while (0)

    LOAD_TILE(0, 0);
    cp_async_commit();

    for (int kt = 0; kt < 8; kt++) {
        if (kt < 7) {
            LOAD_TILE((kt + 1) * 32, (kt + 1) & 1);
            cp_async_commit();
            cp_async_wait<1>();
        } else {
            cp_async_wait<0>();
        }
        __syncthreads();

        const __half* Ab = sm + (kt & 1) * A_BUFH;
        const __half* Bb = Bsm + (kt & 1) * B_BUFH;
#pragma unroll
        for (int ks = 0; ks < 2; ks++) {
            const int kb = ks * 16;
            unsigned af[3][4];
#pragma unroll
            for (int mat = 0; mat < 3; mat++) {
                const __half* Am = Ab + mat * 64 * TSH;
                int mr = rw * 16 + lr;
                af[mat][0] = *(const unsigned*)&Am[ mr      * TSH + kb + 2 * lc    ];
                af[mat][1] = *(const unsigned*)&Am[(mr + 8) * TSH + kb + 2 * lc    ];
                af[mat][2] = *(const unsigned*)&Am[ mr      * TSH + kb + 2 * lc + 8];
                af[mat][3] = *(const unsigned*)&Am[(mr + 8) * TSH + kb + 2 * lc + 8];
            }
#pragma unroll
            for (int p = 0; p < 11; p++) {
                const unsigned* a = af[(p == 0) ? 0 : ((p < 6) ? 1 : 2)];
#pragma unroll
                for (int nt = 0; nt < 2; nt++) {
                    int brow = p * 32 + cw * 16 + nt * 8 + lr;
                    unsigned b0 = *(const unsigned*)&Bb[brow * TSH + kb + 2 * lc    ];
                    unsigned b1 = *(const unsigned*)&Bb[brow * TSH + kb + 2 * lc + 8];
                    asm volatile(
                        "mma.sync.aligned.m16n8k16.row.col.f32.f16.f16.f32 "
                        "{%0,%1,%2,%3}, {%4,%5,%6,%7}, {%8,%9}, {%0,%1,%2,%3};"
                        : "+f"(acc[p][nt][0]), "+f"(acc[p][nt][1]),
                          "+f"(acc[p][nt][2]), "+f"(acc[p][nt][3])
                        : "r"(a[0]), "r"(a[1]), "r"(a[2]), "r"(a[3]),
                          "r"(b0), "r"(b1));
                }
            }
        }
        __syncthreads();
    }
#undef LOAD_TILE

    // ---------------- epilogue: ex_relu + gamma reduction, write out ----------------
#pragma unroll
    for (int h = 0; h < 2; h++) {
        int n = rowbase + rw * 16 + h * 8 + lr;
        if (n >= Nn) continue;
        float ga[Kk];
#pragma unroll
        for (int k = 0; k < Kk; k++) ga[k] = g_gamma[n * Kk + k];
        float dw = g_degw[n];
#pragma unroll
        for (int nt = 0; nt < 2; nt++) {
            int o = q * 32 + cw * 16 + nt * 8 + 2 * lc;
            float b0 = bias[o], b1 = bias[o + 1];
            float y0 = acc[0][nt][h * 2 + 0];
            float y1 = acc[0][nt][h * 2 + 1];
            float r0 = 0.0f, r1 = 0.0f;
#pragma unroll
            for (int k = 0; k < Kk; k++) {
                float cx0 = y0 + acc[1 + k][nt][h * 2 + 0] + dw * b0;
                float cx1 = y1 + acc[1 + k][nt][h * 2 + 1] + dw * b1;
                float cc0 = acc[6 + k][nt][h * 2 + 0];
                float cc1 = acc[6 + k][nt][h * 2 + 1];
                r0 += ga[k] * ex_relu(cx0, cc0);
                r1 += ga[k] * ex_relu(cx1, cc1);
            }
            *(float2*)&out[(size_t)n * Oo + o] = make_float2(r0, r1);
        }
    }
}

extern "C" void kernel_launch(void* const* d_in, const int* in_sizes, int n_in,
                              void* d_out, int out_size) {
    const float* x_vals  = (const float*)d_in[0];
    const void*  x_mask  = (const void*) d_in[1];
    const int*   erow    = (const int*)  d_in[2];
    const int*   ecol    = (const int*)  d_in[3];
    const float* eval    = (const float*)d_in[4];
    const float* logp    = (const float*)d_in[5];
    const float* means   = (const float*)d_in[6];
    const float* logvars = (const float*)d_in[7];
    const float* weight  = (const float*)d_in[8];
    const float* bias    = (const float*)d_in[9];
    float* out = (float*)d_out;
    (void)in_sizes; (void)n_in; (void)out_size;

    static cudaStream_t s2 = 0;
    static cudaEvent_t evFork = 0, evJoin = 0;
    if (!s2) {
        cudaFuncSetAttribute(fused_kernel, cudaFuncAttributeMaxDynamicSharedMemorySize, FUSED_SMEM);
        cudaStreamCreateWithFlags(&s2, cudaStreamNonBlocking);
        cudaEventCreateWithFlags(&evFork, cudaEventDisableTiming);
        cudaEventCreateWithFlags(&evJoin, cudaEventDisableTiming);
    }

    cudaEventRecord(evFork, 0);
    cudaStreamWaitEvent(s2, evFork, 0);

    detect_mask_kernel<<<1, 256, 0, s2>>>((const unsigned int*)x_mask);
    prep_weights_kernel<<<NC, 256, 0, s2>>>(weight, means, logvars);
    mask_gamma_kernel<<<Nn, 256, 0, s2>>>(x_vals, x_mask, means, logp);
    cudaEventRecord(evJoin, s2);

    hist_kernel<<<(Ee + 255) / 256, 256>>>(erow);
    scan_kernel<<<1, 1024>>>();
    scatter_kernel<<<(Ee + 255) / 256, 256>>>(erow, ecol, eval);

    cudaStreamWaitEvent(0, evJoin, 0);

    spmm_kernel<<<Nn, 256>>>();
    dim3 fg(4, (Nn + 63) / 64);
    fused_kernel<<<fg, 256, FUSED_SMEM>>>(bias, out);
}